// round 9
// baseline (speedup 1.0000x reference)
#include <cuda_runtime.h>
#include <math.h>
#include <stdint.h>

// Problem shape (fixed)
#define BB 4
#define TT 2048
#define CC 1024
#define HH 16
#define HD 64
#define MM (BB * TT)     // 8192 rows
#define C3 (3 * CC)      // 3072

// Scratch (device globals — allocation-free per harness rules)
__device__ float g_qkv[(size_t)MM * C3];   // 96 MB (tf32-rounded by QKV gemm)
__device__ float g_y[(size_t)MM * CC];     // 32 MB (tf32-rounded by attention)
__device__ float g_xt[(size_t)MM * CC];    // 32 MB x, tf32-rounded
__device__ float g_wt[(size_t)C3 * CC + (size_t)CC * CC];  // 16 MB weights, tf32-rounded

// ---------------------------------------------------------------------------
// PTX helpers (baseline sm_80+ only: harness PTX target is compute_103,
// which rejects tcgen05/accelerated-arch instructions).
// ---------------------------------------------------------------------------
#define CP_ASYNC16(dst, src) \
    asm volatile("cp.async.cg.shared.global [%0], [%1], 16;\n" \
                 :: "r"(dst), "l"(src) : "memory")
#define CP_COMMIT()  asm volatile("cp.async.commit_group;\n" ::: "memory")
#define CP_WAIT1()   asm volatile("cp.async.wait_group 1;\n" ::: "memory")
#define CP_WAIT0()   asm volatile("cp.async.wait_group 0;\n" ::: "memory")

__device__ __forceinline__ uint32_t smem_u32(const void* p) {
    uint32_t a;
    asm("{ .reg .u64 t; cvta.to.shared.u64 t, %1; cvt.u32.u64 %0, t; }"
        : "=r"(a) : "l"(p));
    return a;
}

__device__ __forceinline__ uint32_t f2tf32(float f) {
    uint32_t r;
    asm("cvt.rna.tf32.f32 %0, %1;" : "=r"(r) : "f"(f));
    return r;
}
__device__ __forceinline__ float f2tf32f(float f) {
    return __uint_as_float(f2tf32(f));
}

__device__ __forceinline__ void mma_tf32(float c[4], const uint32_t a[4],
                                         uint32_t b0, uint32_t b1) {
    asm volatile(
        "mma.sync.aligned.m16n8k8.row.col.f32.tf32.tf32.f32 "
        "{%0,%1,%2,%3}, {%4,%5,%6,%7}, {%8,%9}, {%0,%1,%2,%3};"
        : "+f"(c[0]), "+f"(c[1]), "+f"(c[2]), "+f"(c[3])
        : "r"(a[0]), "r"(a[1]), "r"(a[2]), "r"(a[3]), "r"(b0), "r"(b1));
}

// ---------------------------------------------------------------------------
// Elementwise tf32 rounding pass.
// ---------------------------------------------------------------------------
__global__ __launch_bounds__(256)
void conv_tf32(const float* __restrict__ in, float* __restrict__ out, int n4)
{
    int i = blockIdx.x * 256 + threadIdx.x;
    if (i < n4) {
        float4 v = ((const float4*)in)[i];
        float4 o;
        o.x = f2tf32f(v.x); o.y = f2tf32f(v.y);
        o.z = f2tf32f(v.z); o.w = f2tf32f(v.w);
        ((float4*)out)[i] = o;
    }
}

// ---------------------------------------------------------------------------
// TF32 mma.sync GEMM (unchanged from R8 — passing, 322us on QKV).
// CTA 128x128x32, 128 threads (4 warps, 2x2), warp tile 64x64.
// ---------------------------------------------------------------------------
#define BM 128
#define BN 128
#define BK 32
#define ASTR 36
#define BSTR 136
#define NSTAGE 3
#define AS_SZ (BM * ASTR)   // 4608 floats
#define BS_SZ (BK * BSTR)   // 4352 floats

template<bool ROUND_OUT>
__global__ __launch_bounds__(128)
void gemm_tf32mma(const float* __restrict__ A, const float* __restrict__ B,
                  const float* __restrict__ bias, float* __restrict__ C,
                  int M, int N, int K)
{
    extern __shared__ float smd[];
    float* Asm = smd;                     // [NSTAGE][AS_SZ]
    float* Bsm = smd + NSTAGE * AS_SZ;    // [NSTAGE][BS_SZ]

    const int tid  = threadIdx.x;
    const int wid  = tid >> 5;
    const int lane = tid & 31;
    const int quad = lane >> 2;
    const int tq   = lane & 3;
    const int warpM = wid & 1;
    const int warpN = wid >> 1;
    const int row0 = blockIdx.y * BM;
    const int col0 = blockIdx.x * BN;

    float acc[4][8][4];
    #pragma unroll
    for (int mt = 0; mt < 4; mt++)
        #pragma unroll
        for (int nt = 0; nt < 8; nt++)
            #pragma unroll
            for (int j = 0; j < 4; j++) acc[mt][nt][j] = 0.0f;

    const uint32_t sAu = smem_u32(Asm);
    const uint32_t sBu = smem_u32(Bsm);

    auto load_tile = [&](int kt) {
        const int s = kt % NSTAGE;
        const int k0 = kt * BK;
        #pragma unroll
        for (int i = 0; i < 8; i++) {
            const int id  = tid + i * 128;
            const int ar  = id >> 3;             // 0..127
            const int akc = (id & 7) << 2;       // 0..28
            CP_ASYNC16(sAu + (uint32_t)(s * AS_SZ + ar * ASTR + akc) * 4,
                       A + (size_t)(row0 + ar) * K + k0 + akc);
            const int br  = id >> 5;             // 0..31
            const int bnc = (id & 31) << 2;      // 0..124
            CP_ASYNC16(sBu + (uint32_t)(s * BS_SZ + br * BSTR + bnc) * 4,
                       B + (size_t)(k0 + br) * N + col0 + bnc);
        }
        CP_COMMIT();
    };

    const int NKT = K / BK;   // 32
    load_tile(0);
    load_tile(1);

    for (int kt = 0; kt < NKT; kt++) {
        CP_WAIT1();
        __syncthreads();
        if (kt + 2 < NKT) load_tile(kt + 2);

        const float* as = Asm + (kt % NSTAGE) * AS_SZ;
        const float* bs = Bsm + (kt % NSTAGE) * BS_SZ;

        #pragma unroll
        for (int ks = 0; ks < 4; ks++) {
            uint32_t af[4][4];
            #pragma unroll
            for (int mt = 0; mt < 4; mt++) {
                const int mb = warpM * 64 + mt * 16 + quad;
                const int c  = ks * 8 + tq;
                af[mt][0] = __float_as_uint(as[mb * ASTR + c]);
                af[mt][1] = __float_as_uint(as[(mb + 8) * ASTR + c]);
                af[mt][2] = __float_as_uint(as[mb * ASTR + c + 4]);
                af[mt][3] = __float_as_uint(as[(mb + 8) * ASTR + c + 4]);
            }
            #pragma unroll
            for (int nt = 0; nt < 8; nt++) {
                const int n0 = warpN * 64 + nt * 8 + quad;
                uint32_t b0 = __float_as_uint(bs[(ks * 8 + tq) * BSTR + n0]);
                uint32_t b1 = __float_as_uint(bs[(ks * 8 + tq + 4) * BSTR + n0]);
                #pragma unroll
                for (int mt = 0; mt < 4; mt++)
                    mma_tf32(acc[mt][nt], af[mt], b0, b1);
            }
        }
    }

    #pragma unroll
    for (int mt = 0; mt < 4; mt++) {
        #pragma unroll
        for (int half = 0; half < 2; half++) {
            const int row = row0 + warpM * 64 + mt * 16 + quad + half * 8;
            float* crow = C + (size_t)row * N;
            #pragma unroll
            for (int nt = 0; nt < 8; nt++) {
                const int col = col0 + warpN * 64 + nt * 8 + 2 * tq;
                float2 v;
                v.x = acc[mt][nt][half * 2 + 0] + __ldg(bias + col);
                v.y = acc[mt][nt][half * 2 + 1] + __ldg(bias + col + 1);
                if (ROUND_OUT) { v.x = f2tf32f(v.x); v.y = f2tf32f(v.y); }
                *(float2*)(crow + col) = v;
            }
        }
    }
}

// ---------------------------------------------------------------------------
// Flash attention, tf32 mma.sync. BQ=256: one CTA = 256 threads (8 warps),
// warp owns 32 q rows (2 m16 tiles). KV tiles of 64, cp.async DOUBLE-BUFFERED
// (tile jt+1 loads overlap tile jt compute). qkv pre-rounded tf32.
// Warp w's diagonal tile jd = q0/64 + w/2; tiles beyond jd skipped (flag,
// not continue — barriers stay unconditional).
// Smem: Q 256x68 + 2x(K+V) 64x68 + P 256x68 = 204KB, 1 CTA/SM.
// ---------------------------------------------------------------------------
#define FSTR 68
#define BQ 256
#define KV_SZ (64 * FSTR)   // floats per K (or V) stage

__global__ __launch_bounds__(256, 1)
void flash_attn_mma(const float* __restrict__ qkv, float* __restrict__ y)
{
    extern __shared__ float sm[];
    float* Qs = sm;                         // [256][68]
    float* Kst = Qs + 256 * FSTR;           // [2][64][68]
    float* Vst = Kst + 2 * KV_SZ;           // [2][64][68]
    float* Ps = Vst + 2 * KV_SZ;            // [256][68]

    const int tid  = threadIdx.x;
    const int w    = tid >> 5;
    const int lane = tid & 31;
    const int quad = lane >> 2;
    const int tq   = lane & 3;

    const int b = blockIdx.z, h = blockIdx.y;
    const int q0 = (gridDim.x - 1 - blockIdx.x) * BQ;   // heavy blocks first

    const float* base = qkv + (size_t)b * TT * C3 + h * HD;
    const float* Qg = base;
    const float* Kg = base + CC;
    const float* Vg = base + 2 * CC;

    const uint32_t sKu = smem_u32(Kst);
    const uint32_t sVu = smem_u32(Vst);

    // Load Q tile (256 x 64, already tf32-rounded) — one-time, synchronous.
    #pragma unroll
    for (int it = 0; it < 16; it++) {
        int idx = tid + it * 256;           // 0..4095
        int r  = idx >> 4;                  // 0..255
        int dc = (idx & 15) << 2;           // 0..60
        *(float4*)(Qs + r * FSTR + dc) =
            *(const float4*)(Qg + (size_t)(q0 + r) * C3 + dc);
    }

    // Async K/V tile loader: stage jt&1.
    auto load_kv = [&](int jt) {
        const int s = jt & 1;
        const int k0 = jt << 6;
        #pragma unroll
        for (int it = 0; it < 4; it++) {
            int idx = tid + it * 256;       // 0..1023
            int r  = idx >> 4;              // 0..63
            int dc = (idx & 15) << 2;       // 0..60
            const uint32_t off = (uint32_t)(s * KV_SZ + r * FSTR + dc) * 4;
            CP_ASYNC16(sKu + off, Kg + (size_t)(k0 + r) * C3 + dc);
            CP_ASYNC16(sVu + off, Vg + (size_t)(k0 + r) * C3 + dc);
        }
        CP_COMMIT();
    };

    float mi[2][2], li[2][2];
    #pragma unroll
    for (int mt = 0; mt < 2; mt++) {
        mi[mt][0] = -1e30f; mi[mt][1] = -1e30f;
        li[mt][0] = 0.0f;   li[mt][1] = 0.0f;
    }
    float oacc[2][8][4];
    #pragma unroll
    for (int mt = 0; mt < 2; mt++)
        #pragma unroll
        for (int nt = 0; nt < 8; nt++)
            #pragma unroll
            for (int j = 0; j < 4; j++) oacc[mt][nt][j] = 0.0f;

    const int ntile = (q0 >> 6) + 4;           // kv tiles for this q block
    const int jd    = (q0 >> 6) + (w >> 1);    // this warp's diagonal tile

    load_kv(0);

    for (int jt = 0; jt < ntile; jt++) {
        CP_WAIT0();        // this tile's K/V arrived (issued last iteration)
        __syncthreads();   // visible to all; prev-iter buffer reads all done
        if (jt + 1 < ntile) load_kv(jt + 1);   // overlaps compute below

        const bool active = (jt <= jd);
        const bool diag   = (jt == jd);
        const float* Ks = Kst + (jt & 1) * KV_SZ;
        const float* Vs = Vst + (jt & 1) * KV_SZ;
        const int k0 = jt << 6;

        if (active) {
            // ---- S = Q K^T : warp computes 32 x 64 ----
            float sacc[2][8][4];
            #pragma unroll
            for (int mt = 0; mt < 2; mt++)
                #pragma unroll
                for (int nt = 0; nt < 8; nt++)
                    #pragma unroll
                    for (int j = 0; j < 4; j++) sacc[mt][nt][j] = 0.0f;

            #pragma unroll
            for (int kc = 0; kc < 8; kc++) {
                uint32_t af[2][4];
                #pragma unroll
                for (int mt = 0; mt < 2; mt++) {
                    const int rowA = w * 32 + mt * 16 + quad;
                    af[mt][0] = __float_as_uint(Qs[rowA * FSTR + kc * 8 + tq]);
                    af[mt][1] = __float_as_uint(Qs[(rowA + 8) * FSTR + kc * 8 + tq]);
                    af[mt][2] = __float_as_uint(Qs[rowA * FSTR + kc * 8 + tq + 4]);
                    af[mt][3] = __float_as_uint(Qs[(rowA + 8) * FSTR + kc * 8 + tq + 4]);
                }
                #pragma unroll
                for (int nt = 0; nt < 8; nt++) {
                    uint32_t b0 = __float_as_uint(Ks[(nt * 8 + quad) * FSTR + kc * 8 + tq]);
                    uint32_t b1 = __float_as_uint(Ks[(nt * 8 + quad) * FSTR + kc * 8 + tq + 4]);
                    mma_tf32(sacc[0][nt], af[0], b0, b1);
                    mma_tf32(sacc[1][nt], af[1], b0, b1);
                }
            }

            // ---- scale + causal mask ----
            const float scale = 0.125f;
            #pragma unroll
            for (int mt = 0; mt < 2; mt++) {
                #pragma unroll
                for (int nt = 0; nt < 8; nt++) {
                    #pragma unroll
                    for (int j = 0; j < 4; j++) {
                        float v = sacc[mt][nt][j] * scale;
                        if (diag) {
                            int c = k0 + nt * 8 + 2 * tq + (j & 1);
                            int r = q0 + w * 32 + mt * 16 + quad + (j >> 1) * 8;
                            if (c > r) v = -1e30f;
                        }
                        sacc[mt][nt][j] = v;
                    }
                }
            }

            // ---- online softmax ----
            #pragma unroll
            for (int mt = 0; mt < 2; mt++) {
                float mx0 = -1e30f, mx1 = -1e30f;
                #pragma unroll
                for (int nt = 0; nt < 8; nt++) {
                    mx0 = fmaxf(mx0, fmaxf(sacc[mt][nt][0], sacc[mt][nt][1]));
                    mx1 = fmaxf(mx1, fmaxf(sacc[mt][nt][2], sacc[mt][nt][3]));
                }
                mx0 = fmaxf(mx0, __shfl_xor_sync(0xffffffffu, mx0, 1));
                mx0 = fmaxf(mx0, __shfl_xor_sync(0xffffffffu, mx0, 2));
                mx1 = fmaxf(mx1, __shfl_xor_sync(0xffffffffu, mx1, 1));
                mx1 = fmaxf(mx1, __shfl_xor_sync(0xffffffffu, mx1, 2));

                float mn0 = fmaxf(mi[mt][0], mx0), mn1 = fmaxf(mi[mt][1], mx1);
                float al0 = __expf(mi[mt][0] - mn0), al1 = __expf(mi[mt][1] - mn1);

                float sum0 = 0.0f, sum1 = 0.0f;
                #pragma unroll
                for (int nt = 0; nt < 8; nt++) {
                    float p0 = __expf(sacc[mt][nt][0] - mn0);
                    float p1 = __expf(sacc[mt][nt][1] - mn0);
                    float p2 = __expf(sacc[mt][nt][2] - mn1);
                    float p3 = __expf(sacc[mt][nt][3] - mn1);
                    sum0 += p0 + p1;
                    sum1 += p2 + p3;
                    sacc[mt][nt][0] = p0; sacc[mt][nt][1] = p1;
                    sacc[mt][nt][2] = p2; sacc[mt][nt][3] = p3;
                }
                sum0 += __shfl_xor_sync(0xffffffffu, sum0, 1);
                sum0 += __shfl_xor_sync(0xffffffffu, sum0, 2);
                sum1 += __shfl_xor_sync(0xffffffffu, sum1, 1);
                sum1 += __shfl_xor_sync(0xffffffffu, sum1, 2);

                li[mt][0] = li[mt][0] * al0 + sum0;  mi[mt][0] = mn0;
                li[mt][1] = li[mt][1] * al1 + sum1;  mi[mt][1] = mn1;
                #pragma unroll
                for (int nt = 0; nt < 8; nt++) {
                    oacc[mt][nt][0] *= al0; oacc[mt][nt][1] *= al0;
                    oacc[mt][nt][2] *= al1; oacc[mt][nt][3] *= al1;
                }
            }

            // ---- stage P (tf32 bits) into warp-private rows ----
            __syncwarp();
            #pragma unroll
            for (int mt = 0; mt < 2; mt++) {
                const int rowA = w * 32 + mt * 16 + quad;
                #pragma unroll
                for (int nt = 0; nt < 8; nt++) {
                    float2 p01, p23;
                    p01.x = f2tf32f(sacc[mt][nt][0]);
                    p01.y = f2tf32f(sacc[mt][nt][1]);
                    p23.x = f2tf32f(sacc[mt][nt][2]);
                    p23.y = f2tf32f(sacc[mt][nt][3]);
                    *(float2*)(Ps + rowA * FSTR + nt * 8 + 2 * tq) = p01;
                    *(float2*)(Ps + (rowA + 8) * FSTR + nt * 8 + 2 * tq) = p23;
                }
            }
            __syncwarp();

            // ---- O += P V ----
            #pragma unroll
            for (int kc = 0; kc < 8; kc++) {
                uint32_t af[2][4];
                #pragma unroll
                for (int mt = 0; mt < 2; mt++) {
                    const int rowA = w * 32 + mt * 16 + quad;
                    af[mt][0] = __float_as_uint(Ps[rowA * FSTR + kc * 8 + tq]);
                    af[mt][1] = __float_as_uint(Ps[(rowA + 8) * FSTR + kc * 8 + tq]);
                    af[mt][2] = __float_as_uint(Ps[rowA * FSTR + kc * 8 + tq + 4]);
                    af[mt][3] = __float_as_uint(Ps[(rowA + 8) * FSTR + kc * 8 + tq + 4]);
                }
                #pragma unroll
                for (int nt = 0; nt < 8; nt++) {
                    uint32_t b0 = __float_as_uint(Vs[(kc * 8 + tq) * FSTR + nt * 8 + quad]);
                    uint32_t b1 = __float_as_uint(Vs[(kc * 8 + tq + 4) * FSTR + nt * 8 + quad]);
                    mma_tf32(oacc[0][nt], af[0], b0, b1);
                    mma_tf32(oacc[1][nt], af[1], b0, b1);
                }
            }
        }
    }

    // ---- epilogue: tf32-round (feeds proj gemm) ----
    #pragma unroll
    for (int mt = 0; mt < 2; mt++) {
        const float inv0 = 1.0f / li[mt][0];
        const float inv1 = 1.0f / li[mt][1];
        const size_t r0 = (size_t)b * TT + q0 + w * 32 + mt * 16 + quad;
        #pragma unroll
        for (int nt = 0; nt < 8; nt++) {
            const int col = h * HD + nt * 8 + 2 * tq;
            float2 v0, v1;
            v0.x = f2tf32f(oacc[mt][nt][0] * inv0);
            v0.y = f2tf32f(oacc[mt][nt][1] * inv0);
            v1.x = f2tf32f(oacc[mt][nt][2] * inv1);
            v1.y = f2tf32f(oacc[mt][nt][3] * inv1);
            *(float2*)(y + r0 * CC + col) = v0;
            *(float2*)(y + (r0 + 8) * CC + col) = v1;
        }
    }
}

// ---------------------------------------------------------------------------
// Launch
// ---------------------------------------------------------------------------
extern "C" void kernel_launch(void* const* d_in, const int* in_sizes, int n_in,
                              void* d_out, int out_size)
{
    const float* x     = (const float*)d_in[0];
    const float* Wqkv  = (const float*)d_in[1];
    const float* bqkv  = (const float*)d_in[2];
    const float* Wproj = (const float*)d_in[3];
    const float* bproj = (const float*)d_in[4];
    float* out = (float*)d_out;

    float *qkv, *ybuf, *xt, *wt;
    cudaGetSymbolAddress((void**)&qkv, g_qkv);
    cudaGetSymbolAddress((void**)&ybuf, g_y);
    cudaGetSymbolAddress((void**)&xt, g_xt);
    cudaGetSymbolAddress((void**)&wt, g_wt);
    float* wqkv32  = wt;
    float* wproj32 = wt + (size_t)CC * C3;

    const int smem_gemm = NSTAGE * (AS_SZ + BS_SZ) * sizeof(float);   // 107520
    cudaFuncSetAttribute(gemm_tf32mma<true>,
                         cudaFuncAttributeMaxDynamicSharedMemorySize, smem_gemm);
    cudaFuncSetAttribute(gemm_tf32mma<false>,
                         cudaFuncAttributeMaxDynamicSharedMemorySize, smem_gemm);

    const int smem_attn = (256 + 4 * 64 + 256) * FSTR * sizeof(float);  // 208896
    cudaFuncSetAttribute(flash_attn_mma,
                         cudaFuncAttributeMaxDynamicSharedMemorySize, smem_attn);

    // 0) tf32-round inputs/weights once.
    {
        int n4;
        n4 = (MM * CC) / 4;
        conv_tf32<<<(n4 + 255) / 256, 256>>>(x, xt, n4);
        n4 = (CC * C3) / 4;
        conv_tf32<<<(n4 + 255) / 256, 256>>>(Wqkv, wqkv32, n4);
        n4 = (CC * CC) / 4;
        conv_tf32<<<(n4 + 255) / 256, 256>>>(Wproj, wproj32, n4);
    }

    // 1) QKV projection (output tf32-rounded: feeds attention mma)
    gemm_tf32mma<true><<<dim3(C3 / BN, MM / BM), 128, smem_gemm>>>(
        xt, wqkv32, bqkv, qkv, MM, C3, CC);

    // 2) Causal flash attention -> ybuf (tf32-rounded: feeds proj mma)
    flash_attn_mma<<<dim3(TT / BQ, HH, BB), 256, smem_attn>>>(qkv, ybuf);

    // 3) Output projection (final output: exact fp32)
    gemm_tf32mma<false><<<dim3(CC / BN, MM / BM), 128, smem_gemm>>>(
        ybuf, wproj32, bproj, out, MM, CC, CC);
}

// round 10
// speedup vs baseline: 1.0187x; 1.0187x over previous
#include <cuda_runtime.h>
#include <math.h>
#include <stdint.h>

// Problem shape (fixed)
#define BB 4
#define TT 2048
#define CC 1024
#define HH 16
#define HD 64
#define MM (BB * TT)     // 8192 rows
#define C3 (3 * CC)      // 3072

// Scratch (device globals — allocation-free per harness rules)
__device__ float g_qkv[(size_t)MM * C3];   // 96 MB (tf32-rounded by QKV gemm)
__device__ float g_y[(size_t)MM * CC];     // 32 MB (tf32-rounded by attention)
__device__ float g_xt[(size_t)MM * CC];    // 32 MB x, tf32-rounded
__device__ float g_wt[(size_t)C3 * CC + (size_t)CC * CC];  // 16 MB weights, tf32-rounded

// ---------------------------------------------------------------------------
// PTX helpers (baseline sm_80+ only: harness PTX target is compute_103,
// which rejects tcgen05/accelerated-arch instructions).
// ---------------------------------------------------------------------------
#define CP_ASYNC16(dst, src) \
    asm volatile("cp.async.cg.shared.global [%0], [%1], 16;\n" \
                 :: "r"(dst), "l"(src) : "memory")
#define CP_COMMIT()  asm volatile("cp.async.commit_group;\n" ::: "memory")
#define CP_WAIT1()   asm volatile("cp.async.wait_group 1;\n" ::: "memory")

__device__ __forceinline__ uint32_t smem_u32(const void* p) {
    uint32_t a;
    asm("{ .reg .u64 t; cvta.to.shared.u64 t, %1; cvt.u32.u64 %0, t; }"
        : "=r"(a) : "l"(p));
    return a;
}

__device__ __forceinline__ uint32_t f2tf32(float f) {
    uint32_t r;
    asm("cvt.rna.tf32.f32 %0, %1;" : "=r"(r) : "f"(f));
    return r;
}
__device__ __forceinline__ float f2tf32f(float f) {
    return __uint_as_float(f2tf32(f));
}

__device__ __forceinline__ void mma_tf32(float c[4], const uint32_t a[4],
                                         uint32_t b0, uint32_t b1) {
    asm volatile(
        "mma.sync.aligned.m16n8k8.row.col.f32.tf32.tf32.f32 "
        "{%0,%1,%2,%3}, {%4,%5,%6,%7}, {%8,%9}, {%0,%1,%2,%3};"
        : "+f"(c[0]), "+f"(c[1]), "+f"(c[2]), "+f"(c[3])
        : "r"(a[0]), "r"(a[1]), "r"(a[2]), "r"(a[3]), "r"(b0), "r"(b1));
}

// ---------------------------------------------------------------------------
// Elementwise tf32 rounding pass.
// ---------------------------------------------------------------------------
__global__ __launch_bounds__(256)
void conv_tf32(const float* __restrict__ in, float* __restrict__ out, int n4)
{
    int i = blockIdx.x * 256 + threadIdx.x;
    if (i < n4) {
        float4 v = ((const float4*)in)[i];
        float4 o;
        o.x = f2tf32f(v.x); o.y = f2tf32f(v.y);
        o.z = f2tf32f(v.z); o.w = f2tf32f(v.w);
        ((float4*)out)[i] = o;
    }
}

// ---------------------------------------------------------------------------
// TF32 mma.sync GEMM: C = A @ B + bias. Operands pre-rounded to tf32.
// CTA 128x128x32, 256 threads (8 warps: 2M x 4N), warp tile 64x32.
// 4 warps/SMSP (2 CTAs/SM) to hide HMMA/LDS latency.
// 3-stage cp.async pipeline, ONE syncthreads per 32-wide k-tile.
// A smem [m][k] stride 36, B smem [k][n] stride 136 (bank-bijective frags).
// ---------------------------------------------------------------------------
#define BM 128
#define BN 128
#define BK 32
#define ASTR 36
#define BSTR 136
#define NSTAGE 3
#define AS_SZ (BM * ASTR)   // 4608 floats
#define BS_SZ (BK * BSTR)   // 4352 floats

template<bool ROUND_OUT>
__global__ __launch_bounds__(256, 2)
void gemm_tf32mma(const float* __restrict__ A, const float* __restrict__ B,
                  const float* __restrict__ bias, float* __restrict__ C,
                  int M, int N, int K)
{
    extern __shared__ float smd[];
    float* Asm = smd;                     // [NSTAGE][AS_SZ]
    float* Bsm = smd + NSTAGE * AS_SZ;    // [NSTAGE][BS_SZ]

    const int tid  = threadIdx.x;
    const int wid  = tid >> 5;
    const int lane = tid & 31;
    const int quad = lane >> 2;
    const int tq   = lane & 3;
    const int warpM = wid & 1;     // 0..1 -> 64 rows
    const int warpN = wid >> 1;    // 0..3 -> 32 cols
    const int row0 = blockIdx.y * BM;
    const int col0 = blockIdx.x * BN;

    float acc[4][4][4];
    #pragma unroll
    for (int mt = 0; mt < 4; mt++)
        #pragma unroll
        for (int nt = 0; nt < 4; nt++)
            #pragma unroll
            for (int j = 0; j < 4; j++) acc[mt][nt][j] = 0.0f;

    const uint32_t sAu = smem_u32(Asm);
    const uint32_t sBu = smem_u32(Bsm);

    auto load_tile = [&](int kt) {
        const int s = kt % NSTAGE;
        const int k0 = kt * BK;
        #pragma unroll
        for (int i = 0; i < 4; i++) {
            const int id  = tid + i * 256;       // 0..1023
            const int ar  = id >> 3;             // 0..127
            const int akc = (id & 7) << 2;       // 0..28
            CP_ASYNC16(sAu + (uint32_t)(s * AS_SZ + ar * ASTR + akc) * 4,
                       A + (size_t)(row0 + ar) * K + k0 + akc);
            const int br  = id >> 5;             // 0..31
            const int bnc = (id & 31) << 2;      // 0..124
            CP_ASYNC16(sBu + (uint32_t)(s * BS_SZ + br * BSTR + bnc) * 4,
                       B + (size_t)(k0 + br) * N + col0 + bnc);
        }
        CP_COMMIT();
    };

    const int NKT = K / BK;   // 32
    load_tile(0);
    load_tile(1);

    for (int kt = 0; kt < NKT; kt++) {
        CP_WAIT1();          // stage kt complete (<=1 group pending)
        __syncthreads();     // all warps past reads of stage (kt-1)%3
        if (kt + 2 < NKT) load_tile(kt + 2);

        const float* as = Asm + (kt % NSTAGE) * AS_SZ;
        const float* bs = Bsm + (kt % NSTAGE) * BS_SZ;

        #pragma unroll
        for (int ks = 0; ks < 4; ks++) {
            uint32_t af[4][4];
            #pragma unroll
            for (int mt = 0; mt < 4; mt++) {
                const int mb = warpM * 64 + mt * 16 + quad;
                const int c  = ks * 8 + tq;
                af[mt][0] = __float_as_uint(as[mb * ASTR + c]);
                af[mt][1] = __float_as_uint(as[(mb + 8) * ASTR + c]);
                af[mt][2] = __float_as_uint(as[mb * ASTR + c + 4]);
                af[mt][3] = __float_as_uint(as[(mb + 8) * ASTR + c + 4]);
            }
            #pragma unroll
            for (int nt = 0; nt < 4; nt++) {
                const int n0 = warpN * 32 + nt * 8 + quad;
                uint32_t b0 = __float_as_uint(bs[(ks * 8 + tq) * BSTR + n0]);
                uint32_t b1 = __float_as_uint(bs[(ks * 8 + tq + 4) * BSTR + n0]);
                #pragma unroll
                for (int mt = 0; mt < 4; mt++)
                    mma_tf32(acc[mt][nt], af[mt], b0, b1);
            }
        }
    }

    // Epilogue
    #pragma unroll
    for (int mt = 0; mt < 4; mt++) {
        #pragma unroll
        for (int half = 0; half < 2; half++) {
            const int row = row0 + warpM * 64 + mt * 16 + quad + half * 8;
            float* crow = C + (size_t)row * N;
            #pragma unroll
            for (int nt = 0; nt < 4; nt++) {
                const int col = col0 + warpN * 32 + nt * 8 + 2 * tq;
                float2 v;
                v.x = acc[mt][nt][half * 2 + 0] + __ldg(bias + col);
                v.y = acc[mt][nt][half * 2 + 1] + __ldg(bias + col + 1);
                if (ROUND_OUT) { v.x = f2tf32f(v.x); v.y = f2tf32f(v.y); }
                *(float2*)(crow + col) = v;
            }
        }
    }
}

// ---------------------------------------------------------------------------
// Flash attention, tf32 mma.sync — R8 version (best measured: ~345us).
// BQ=128: 128 threads (4 warps), warp owns 32 q rows. KV tiles of 64.
// Dedicated 128-row P buffer. Smem 104448 B, 2 CTAs/SM.
// ---------------------------------------------------------------------------
#define FSTR 68
#define BQ 128

__global__ __launch_bounds__(128, 2)
void flash_attn_mma(const float* __restrict__ qkv, float* __restrict__ y)
{
    extern __shared__ float sm[];
    float* Qs = sm;                    // [128][68]
    float* Ks = Qs + 128 * FSTR;       // [64][68]
    float* Vs = Ks + 64 * FSTR;        // [64][68]
    float* Ps = Vs + 64 * FSTR;        // [128][68]

    const int tid  = threadIdx.x;
    const int w    = tid >> 5;
    const int lane = tid & 31;
    const int quad = lane >> 2;
    const int tq   = lane & 3;

    const int b = blockIdx.z, h = blockIdx.y;
    const int q0 = (gridDim.x - 1 - blockIdx.x) * BQ;   // heavy tiles first

    const float* base = qkv + (size_t)b * TT * C3 + h * HD;
    const float* Qg = base;
    const float* Kg = base + CC;
    const float* Vg = base + 2 * CC;

    // Load Q tile (128 x 64, already tf32-rounded).
    #pragma unroll
    for (int it = 0; it < 16; it++) {
        int idx = tid + it * 128;
        int r  = idx >> 4;
        int dc = (idx & 15) << 2;
        *(float4*)(Qs + r * FSTR + dc) =
            *(const float4*)(Qg + (size_t)(q0 + r) * C3 + dc);
    }

    float mi[2][2], li[2][2];
    #pragma unroll
    for (int mt = 0; mt < 2; mt++) {
        mi[mt][0] = -1e30f; mi[mt][1] = -1e30f;
        li[mt][0] = 0.0f;   li[mt][1] = 0.0f;
    }
    float oacc[2][8][4];
    #pragma unroll
    for (int mt = 0; mt < 2; mt++)
        #pragma unroll
        for (int nt = 0; nt < 8; nt++)
            #pragma unroll
            for (int j = 0; j < 4; j++) oacc[mt][nt][j] = 0.0f;

    const int ntile = (q0 >> 6) + 2;
    for (int jt = 0; jt < ntile; jt++) {
        const int k0 = jt << 6;
        __syncthreads();   // prev-iter K/V/P reads complete before overwrite

        // Load K and V tiles (64 x 64 each).
        #pragma unroll
        for (int it = 0; it < 8; it++) {
            int idx = tid + it * 128;
            int r  = idx >> 4;
            int dc = (idx & 15) << 2;
            *(float4*)(Ks + r * FSTR + dc) =
                *(const float4*)(Kg + (size_t)(k0 + r) * C3 + dc);
            *(float4*)(Vs + r * FSTR + dc) =
                *(const float4*)(Vg + (size_t)(k0 + r) * C3 + dc);
        }
        __syncthreads();

        // Warps 0,1 are fully masked on the last tile: skip compute entirely.
        if (jt == ntile - 1 && w < 2) continue;

        const bool diag = (w < 2) ? (jt == ntile - 2) : (jt == ntile - 1);

        // ---- S = Q K^T : warp computes 32 x 64 ----
        float sacc[2][8][4];
        #pragma unroll
        for (int mt = 0; mt < 2; mt++)
            #pragma unroll
            for (int nt = 0; nt < 8; nt++)
                #pragma unroll
                for (int j = 0; j < 4; j++) sacc[mt][nt][j] = 0.0f;

        #pragma unroll
        for (int kc = 0; kc < 8; kc++) {
            uint32_t af[2][4];
            #pragma unroll
            for (int mt = 0; mt < 2; mt++) {
                const int rowA = w * 32 + mt * 16 + quad;
                af[mt][0] = __float_as_uint(Qs[rowA * FSTR + kc * 8 + tq]);
                af[mt][1] = __float_as_uint(Qs[(rowA + 8) * FSTR + kc * 8 + tq]);
                af[mt][2] = __float_as_uint(Qs[rowA * FSTR + kc * 8 + tq + 4]);
                af[mt][3] = __float_as_uint(Qs[(rowA + 8) * FSTR + kc * 8 + tq + 4]);
            }
            #pragma unroll
            for (int nt = 0; nt < 8; nt++) {
                uint32_t b0 = __float_as_uint(Ks[(nt * 8 + quad) * FSTR + kc * 8 + tq]);
                uint32_t b1 = __float_as_uint(Ks[(nt * 8 + quad) * FSTR + kc * 8 + tq + 4]);
                mma_tf32(sacc[0][nt], af[0], b0, b1);
                mma_tf32(sacc[1][nt], af[1], b0, b1);
            }
        }

        // ---- scale + causal mask ----
        const float scale = 0.125f;
        #pragma unroll
        for (int mt = 0; mt < 2; mt++) {
            #pragma unroll
            for (int nt = 0; nt < 8; nt++) {
                #pragma unroll
                for (int j = 0; j < 4; j++) {
                    float v = sacc[mt][nt][j] * scale;
                    if (diag) {
                        int c = k0 + nt * 8 + 2 * tq + (j & 1);
                        int r = q0 + w * 32 + mt * 16 + quad + (j >> 1) * 8;
                        if (c > r) v = -1e30f;
                    }
                    sacc[mt][nt][j] = v;
                }
            }
        }

        // ---- online softmax (per mt: rows quad, quad+8; reduce over tq) ----
        #pragma unroll
        for (int mt = 0; mt < 2; mt++) {
            float mx0 = -1e30f, mx1 = -1e30f;
            #pragma unroll
            for (int nt = 0; nt < 8; nt++) {
                mx0 = fmaxf(mx0, fmaxf(sacc[mt][nt][0], sacc[mt][nt][1]));
                mx1 = fmaxf(mx1, fmaxf(sacc[mt][nt][2], sacc[mt][nt][3]));
            }
            mx0 = fmaxf(mx0, __shfl_xor_sync(0xffffffffu, mx0, 1));
            mx0 = fmaxf(mx0, __shfl_xor_sync(0xffffffffu, mx0, 2));
            mx1 = fmaxf(mx1, __shfl_xor_sync(0xffffffffu, mx1, 1));
            mx1 = fmaxf(mx1, __shfl_xor_sync(0xffffffffu, mx1, 2));

            float mn0 = fmaxf(mi[mt][0], mx0), mn1 = fmaxf(mi[mt][1], mx1);
            float al0 = __expf(mi[mt][0] - mn0), al1 = __expf(mi[mt][1] - mn1);

            float sum0 = 0.0f, sum1 = 0.0f;
            #pragma unroll
            for (int nt = 0; nt < 8; nt++) {
                float p0 = __expf(sacc[mt][nt][0] - mn0);
                float p1 = __expf(sacc[mt][nt][1] - mn0);
                float p2 = __expf(sacc[mt][nt][2] - mn1);
                float p3 = __expf(sacc[mt][nt][3] - mn1);
                sum0 += p0 + p1;
                sum1 += p2 + p3;
                sacc[mt][nt][0] = p0; sacc[mt][nt][1] = p1;
                sacc[mt][nt][2] = p2; sacc[mt][nt][3] = p3;
            }
            sum0 += __shfl_xor_sync(0xffffffffu, sum0, 1);
            sum0 += __shfl_xor_sync(0xffffffffu, sum0, 2);
            sum1 += __shfl_xor_sync(0xffffffffu, sum1, 1);
            sum1 += __shfl_xor_sync(0xffffffffu, sum1, 2);

            li[mt][0] = li[mt][0] * al0 + sum0;  mi[mt][0] = mn0;
            li[mt][1] = li[mt][1] * al1 + sum1;  mi[mt][1] = mn1;
            #pragma unroll
            for (int nt = 0; nt < 8; nt++) {
                oacc[mt][nt][0] *= al0; oacc[mt][nt][1] *= al0;
                oacc[mt][nt][2] *= al1; oacc[mt][nt][3] *= al1;
            }
        }

        // ---- stage P (tf32 bits) into warp-private rows ----
        __syncwarp();
        #pragma unroll
        for (int mt = 0; mt < 2; mt++) {
            const int rowA = w * 32 + mt * 16 + quad;
            #pragma unroll
            for (int nt = 0; nt < 8; nt++) {
                float2 p01, p23;
                p01.x = f2tf32f(sacc[mt][nt][0]);
                p01.y = f2tf32f(sacc[mt][nt][1]);
                p23.x = f2tf32f(sacc[mt][nt][2]);
                p23.y = f2tf32f(sacc[mt][nt][3]);
                *(float2*)(Ps + rowA * FSTR + nt * 8 + 2 * tq) = p01;
                *(float2*)(Ps + (rowA + 8) * FSTR + nt * 8 + 2 * tq) = p23;
            }
        }
        __syncwarp();

        // ---- O += P V ----
        #pragma unroll
        for (int kc = 0; kc < 8; kc++) {
            uint32_t af[2][4];
            #pragma unroll
            for (int mt = 0; mt < 2; mt++) {
                const int rowA = w * 32 + mt * 16 + quad;
                af[mt][0] = __float_as_uint(Ps[rowA * FSTR + kc * 8 + tq]);
                af[mt][1] = __float_as_uint(Ps[(rowA + 8) * FSTR + kc * 8 + tq]);
                af[mt][2] = __float_as_uint(Ps[rowA * FSTR + kc * 8 + tq + 4]);
                af[mt][3] = __float_as_uint(Ps[(rowA + 8) * FSTR + kc * 8 + tq + 4]);
            }
            #pragma unroll
            for (int nt = 0; nt < 8; nt++) {
                uint32_t b0 = __float_as_uint(Vs[(kc * 8 + tq) * FSTR + nt * 8 + quad]);
                uint32_t b1 = __float_as_uint(Vs[(kc * 8 + tq + 4) * FSTR + nt * 8 + quad]);
                mma_tf32(oacc[0][nt], af[0], b0, b1);
                mma_tf32(oacc[1][nt], af[1], b0, b1);
            }
        }
    }

    // ---- epilogue: tf32-round (feeds proj gemm) ----
    #pragma unroll
    for (int mt = 0; mt < 2; mt++) {
        const float inv0 = 1.0f / li[mt][0];
        const float inv1 = 1.0f / li[mt][1];
        const size_t r0 = (size_t)b * TT + q0 + w * 32 + mt * 16 + quad;
        #pragma unroll
        for (int nt = 0; nt < 8; nt++) {
            const int col = h * HD + nt * 8 + 2 * tq;
            float2 v0, v1;
            v0.x = f2tf32f(oacc[mt][nt][0] * inv0);
            v0.y = f2tf32f(oacc[mt][nt][1] * inv0);
            v1.x = f2tf32f(oacc[mt][nt][2] * inv1);
            v1.y = f2tf32f(oacc[mt][nt][3] * inv1);
            *(float2*)(y + r0 * CC + col) = v0;
            *(float2*)(y + (r0 + 8) * CC + col) = v1;
        }
    }
}

// ---------------------------------------------------------------------------
// Launch
// ---------------------------------------------------------------------------
extern "C" void kernel_launch(void* const* d_in, const int* in_sizes, int n_in,
                              void* d_out, int out_size)
{
    const float* x     = (const float*)d_in[0];
    const float* Wqkv  = (const float*)d_in[1];
    const float* bqkv  = (const float*)d_in[2];
    const float* Wproj = (const float*)d_in[3];
    const float* bproj = (const float*)d_in[4];
    float* out = (float*)d_out;

    float *qkv, *ybuf, *xt, *wt;
    cudaGetSymbolAddress((void**)&qkv, g_qkv);
    cudaGetSymbolAddress((void**)&ybuf, g_y);
    cudaGetSymbolAddress((void**)&xt, g_xt);
    cudaGetSymbolAddress((void**)&wt, g_wt);
    float* wqkv32  = wt;
    float* wproj32 = wt + (size_t)CC * C3;

    const int smem_gemm = NSTAGE * (AS_SZ + BS_SZ) * sizeof(float);   // 107520
    cudaFuncSetAttribute(gemm_tf32mma<true>,
                         cudaFuncAttributeMaxDynamicSharedMemorySize, smem_gemm);
    cudaFuncSetAttribute(gemm_tf32mma<false>,
                         cudaFuncAttributeMaxDynamicSharedMemorySize, smem_gemm);

    const int smem_attn = (128 + 64 + 64 + 128) * FSTR * sizeof(float);  // 104448
    cudaFuncSetAttribute(flash_attn_mma,
                         cudaFuncAttributeMaxDynamicSharedMemorySize, smem_attn);

    // 0) tf32-round inputs/weights once.
    {
        int n4;
        n4 = (MM * CC) / 4;
        conv_tf32<<<(n4 + 255) / 256, 256>>>(x, xt, n4);
        n4 = (CC * C3) / 4;
        conv_tf32<<<(n4 + 255) / 256, 256>>>(Wqkv, wqkv32, n4);
        n4 = (CC * CC) / 4;
        conv_tf32<<<(n4 + 255) / 256, 256>>>(Wproj, wproj32, n4);
    }

    // 1) QKV projection (output tf32-rounded: feeds attention mma)
    gemm_tf32mma<true><<<dim3(C3 / BN, MM / BM), 256, smem_gemm>>>(
        xt, wqkv32, bqkv, qkv, MM, C3, CC);

    // 2) Causal flash attention -> ybuf (tf32-rounded: feeds proj mma)
    flash_attn_mma<<<dim3(TT / BQ, HH, BB), 128, smem_attn>>>(qkv, ybuf);

    // 3) Output projection (final output: exact fp32)
    gemm_tf32mma<false><<<dim3(CC / BN, MM / BM), 256, smem_gemm>>>(
        ybuf, wproj32, bproj, out, MM, CC, CC);
}

// round 11
// speedup vs baseline: 1.0374x; 1.0184x over previous
#include <cuda_runtime.h>
#include <math.h>
#include <stdint.h>

// Problem shape (fixed)
#define BB 4
#define TT 2048
#define CC 1024
#define HH 16
#define HD 64
#define MM (BB * TT)     // 8192 rows
#define C3 (3 * CC)      // 3072

// Scratch (device globals — allocation-free per harness rules)
__device__ float g_qkv[(size_t)MM * C3];   // 96 MB (tf32-rounded by QKV gemm)
__device__ float g_y[(size_t)MM * CC];     // 32 MB (tf32-rounded by attention)
__device__ float g_xt[(size_t)MM * CC];    // 32 MB x, tf32-rounded
__device__ float g_wt[(size_t)C3 * CC + (size_t)CC * CC];  // 16 MB weights, tf32-rounded

// ---------------------------------------------------------------------------
// PTX helpers (baseline sm_80+ only: harness PTX target is compute_103,
// which rejects tcgen05/accelerated-arch instructions).
// ---------------------------------------------------------------------------
#define CP_ASYNC16(dst, src) \
    asm volatile("cp.async.cg.shared.global [%0], [%1], 16;\n" \
                 :: "r"(dst), "l"(src) : "memory")
#define CP_COMMIT()  asm volatile("cp.async.commit_group;\n" ::: "memory")
#define CP_WAIT1()   asm volatile("cp.async.wait_group 1;\n" ::: "memory")

__device__ __forceinline__ uint32_t smem_u32(const void* p) {
    uint32_t a;
    asm("{ .reg .u64 t; cvta.to.shared.u64 t, %1; cvt.u32.u64 %0, t; }"
        : "=r"(a) : "l"(p));
    return a;
}

__device__ __forceinline__ uint32_t f2tf32(float f) {
    uint32_t r;
    asm("cvt.rna.tf32.f32 %0, %1;" : "=r"(r) : "f"(f));
    return r;
}
__device__ __forceinline__ float f2tf32f(float f) {
    return __uint_as_float(f2tf32(f));
}

__device__ __forceinline__ void mma_tf32(float c[4], const uint32_t a[4],
                                         uint32_t b0, uint32_t b1) {
    asm volatile(
        "mma.sync.aligned.m16n8k8.row.col.f32.tf32.tf32.f32 "
        "{%0,%1,%2,%3}, {%4,%5,%6,%7}, {%8,%9}, {%0,%1,%2,%3};"
        : "+f"(c[0]), "+f"(c[1]), "+f"(c[2]), "+f"(c[3])
        : "r"(a[0]), "r"(a[1]), "r"(a[2]), "r"(a[3]), "r"(b0), "r"(b1));
}

// ---------------------------------------------------------------------------
// Elementwise tf32 rounding pass.
// ---------------------------------------------------------------------------
__global__ __launch_bounds__(256)
void conv_tf32(const float* __restrict__ in, float* __restrict__ out, int n4)
{
    int i = blockIdx.x * 256 + threadIdx.x;
    if (i < n4) {
        float4 v = ((const float4*)in)[i];
        float4 o;
        o.x = f2tf32f(v.x); o.y = f2tf32f(v.y);
        o.z = f2tf32f(v.z); o.w = f2tf32f(v.w);
        ((float4*)out)[i] = o;
    }
}

// ---------------------------------------------------------------------------
// TF32 mma.sync GEMM (R10 version — 320us on QKV, at the legacy-HMMA ceiling).
// CTA 128x128x32, 256 threads (8 warps: 2M x 4N), warp tile 64x32.
// ---------------------------------------------------------------------------
#define BM 128
#define BN 128
#define BK 32
#define ASTR 36
#define BSTR 136
#define NSTAGE 3
#define AS_SZ (BM * ASTR)   // 4608 floats
#define BS_SZ (BK * BSTR)   // 4352 floats

template<bool ROUND_OUT>
__global__ __launch_bounds__(256, 2)
void gemm_tf32mma(const float* __restrict__ A, const float* __restrict__ B,
                  const float* __restrict__ bias, float* __restrict__ C,
                  int M, int N, int K)
{
    extern __shared__ float smd[];
    float* Asm = smd;                     // [NSTAGE][AS_SZ]
    float* Bsm = smd + NSTAGE * AS_SZ;    // [NSTAGE][BS_SZ]

    const int tid  = threadIdx.x;
    const int wid  = tid >> 5;
    const int lane = tid & 31;
    const int quad = lane >> 2;
    const int tq   = lane & 3;
    const int warpM = wid & 1;
    const int warpN = wid >> 1;
    const int row0 = blockIdx.y * BM;
    const int col0 = blockIdx.x * BN;

    float acc[4][4][4];
    #pragma unroll
    for (int mt = 0; mt < 4; mt++)
        #pragma unroll
        for (int nt = 0; nt < 4; nt++)
            #pragma unroll
            for (int j = 0; j < 4; j++) acc[mt][nt][j] = 0.0f;

    const uint32_t sAu = smem_u32(Asm);
    const uint32_t sBu = smem_u32(Bsm);

    auto load_tile = [&](int kt) {
        const int s = kt % NSTAGE;
        const int k0 = kt * BK;
        #pragma unroll
        for (int i = 0; i < 4; i++) {
            const int id  = tid + i * 256;
            const int ar  = id >> 3;
            const int akc = (id & 7) << 2;
            CP_ASYNC16(sAu + (uint32_t)(s * AS_SZ + ar * ASTR + akc) * 4,
                       A + (size_t)(row0 + ar) * K + k0 + akc);
            const int br  = id >> 5;
            const int bnc = (id & 31) << 2;
            CP_ASYNC16(sBu + (uint32_t)(s * BS_SZ + br * BSTR + bnc) * 4,
                       B + (size_t)(k0 + br) * N + col0 + bnc);
        }
        CP_COMMIT();
    };

    const int NKT = K / BK;   // 32
    load_tile(0);
    load_tile(1);

    for (int kt = 0; kt < NKT; kt++) {
        CP_WAIT1();
        __syncthreads();
        if (kt + 2 < NKT) load_tile(kt + 2);

        const float* as = Asm + (kt % NSTAGE) * AS_SZ;
        const float* bs = Bsm + (kt % NSTAGE) * BS_SZ;

        #pragma unroll
        for (int ks = 0; ks < 4; ks++) {
            uint32_t af[4][4];
            #pragma unroll
            for (int mt = 0; mt < 4; mt++) {
                const int mb = warpM * 64 + mt * 16 + quad;
                const int c  = ks * 8 + tq;
                af[mt][0] = __float_as_uint(as[mb * ASTR + c]);
                af[mt][1] = __float_as_uint(as[(mb + 8) * ASTR + c]);
                af[mt][2] = __float_as_uint(as[mb * ASTR + c + 4]);
                af[mt][3] = __float_as_uint(as[(mb + 8) * ASTR + c + 4]);
            }
            #pragma unroll
            for (int nt = 0; nt < 4; nt++) {
                const int n0 = warpN * 32 + nt * 8 + quad;
                uint32_t b0 = __float_as_uint(bs[(ks * 8 + tq) * BSTR + n0]);
                uint32_t b1 = __float_as_uint(bs[(ks * 8 + tq + 4) * BSTR + n0]);
                #pragma unroll
                for (int mt = 0; mt < 4; mt++)
                    mma_tf32(acc[mt][nt], af[mt], b0, b1);
            }
        }
    }

    #pragma unroll
    for (int mt = 0; mt < 4; mt++) {
        #pragma unroll
        for (int half = 0; half < 2; half++) {
            const int row = row0 + warpM * 64 + mt * 16 + quad + half * 8;
            float* crow = C + (size_t)row * N;
            #pragma unroll
            for (int nt = 0; nt < 4; nt++) {
                const int col = col0 + warpN * 32 + nt * 8 + 2 * tq;
                float2 v;
                v.x = acc[mt][nt][half * 2 + 0] + __ldg(bias + col);
                v.y = acc[mt][nt][half * 2 + 1] + __ldg(bias + col + 1);
                if (ROUND_OUT) { v.x = f2tf32f(v.x); v.y = f2tf32f(v.y); }
                *(float2*)(crow + col) = v;
            }
        }
    }
}

// ---------------------------------------------------------------------------
// Flash attention, tf32 mma.sync. BQ=128, 128 threads (4 warps).
// NEW vs R8:
//  - Q fragments hoisted into registers (loop-invariant): S-phase A-frag LDS
//    eliminated; Qs smem is dead after the prologue.
//  - P buffer ALIASES Qs (both 128x68 — dimensionally exact).
//  - K/V double-buffered via cp.async; prefetch overlaps compute.
// Smem: P/Q 128x68 + 2x(K+V) 64x68 = 104448 B -> 2 CTAs/SM.
// ---------------------------------------------------------------------------
#define FSTR 68
#define BQ 128
#define KV_SZ (64 * FSTR)

__global__ __launch_bounds__(128, 2)
void flash_attn_mma(const float* __restrict__ qkv, float* __restrict__ y)
{
    extern __shared__ float sm[];
    float* Qs  = sm;                    // [128][68] prologue staging
    float* Ps  = sm;                    // alias — Qs dead after frag hoist
    float* Kst = sm + 128 * FSTR;       // [2][64][68]
    float* Vst = Kst + 2 * KV_SZ;       // [2][64][68]

    const int tid  = threadIdx.x;
    const int w    = tid >> 5;
    const int lane = tid & 31;
    const int quad = lane >> 2;
    const int tq   = lane & 3;

    const int b = blockIdx.z, h = blockIdx.y;
    const int q0 = (gridDim.x - 1 - blockIdx.x) * BQ;   // heavy tiles first

    const float* base = qkv + (size_t)b * TT * C3 + h * HD;
    const float* Qg = base;
    const float* Kg = base + CC;
    const float* Vg = base + 2 * CC;

    const uint32_t sKu = smem_u32(Kst);
    const uint32_t sVu = smem_u32(Vst);

    // Prologue: stage Q tile (128 x 64, already tf32-rounded) into smem.
    #pragma unroll
    for (int it = 0; it < 16; it++) {
        int idx = tid + it * 128;
        int r  = idx >> 4;
        int dc = (idx & 15) << 2;
        *(float4*)(Qs + r * FSTR + dc) =
            *(const float4*)(Qg + (size_t)(q0 + r) * C3 + dc);
    }

    // Async K/V tile loader: stage jt&1.
    auto load_kv = [&](int jt) {
        const int s = jt & 1;
        const int k0 = jt << 6;
        #pragma unroll
        for (int it = 0; it < 8; it++) {
            int idx = tid + it * 128;       // 0..1023
            int r  = idx >> 4;              // 0..63
            int dc = (idx & 15) << 2;       // 0..60
            const uint32_t off = (uint32_t)(s * KV_SZ + r * FSTR + dc) * 4;
            CP_ASYNC16(sKu + off, Kg + (size_t)(k0 + r) * C3 + dc);
            CP_ASYNC16(sVu + off, Vg + (size_t)(k0 + r) * C3 + dc);
        }
        CP_COMMIT();
    };

    __syncthreads();     // Qs visible to all warps
    load_kv(0);          // overlap kv0 fetch with Q fragment extraction

    // Hoist Q fragments into registers (loop-invariant).
    uint32_t qf[8][2][4];
    #pragma unroll
    for (int kc = 0; kc < 8; kc++)
        #pragma unroll
        for (int mt = 0; mt < 2; mt++) {
            const int rowA = w * 32 + mt * 16 + quad;
            qf[kc][mt][0] = __float_as_uint(Qs[rowA * FSTR + kc * 8 + tq]);
            qf[kc][mt][1] = __float_as_uint(Qs[(rowA + 8) * FSTR + kc * 8 + tq]);
            qf[kc][mt][2] = __float_as_uint(Qs[rowA * FSTR + kc * 8 + tq + 4]);
            qf[kc][mt][3] = __float_as_uint(Qs[(rowA + 8) * FSTR + kc * 8 + tq + 4]);
        }

    float mi[2][2], li[2][2];
    #pragma unroll
    for (int mt = 0; mt < 2; mt++) {
        mi[mt][0] = -1e30f; mi[mt][1] = -1e30f;
        li[mt][0] = 0.0f;   li[mt][1] = 0.0f;
    }
    float oacc[2][8][4];
    #pragma unroll
    for (int mt = 0; mt < 2; mt++)
        #pragma unroll
        for (int nt = 0; nt < 8; nt++)
            #pragma unroll
            for (int j = 0; j < 4; j++) oacc[mt][nt][j] = 0.0f;

    const int ntile = (q0 >> 6) + 2;
    for (int jt = 0; jt < ntile; jt++) {
        const int k0 = jt << 6;
        // All warps done reading stage (jt+1)&1 (used in iter jt-1) and Ps.
        __syncthreads();
        if (jt + 1 < ntile) load_kv(jt + 1);
        CP_WAIT1();        // tile jt arrived (jt+1 may be pending)
        __syncthreads();   // cross-thread visibility of cp.async data

        // Warps 0,1 fully masked on the last tile: skip (last iter only —
        // no further barriers inside the loop after this point).
        if (jt == ntile - 1 && w < 2) continue;

        const bool diag = (w < 2) ? (jt == ntile - 2) : (jt == ntile - 1);
        const float* Ks = Kst + (jt & 1) * KV_SZ;
        const float* Vs = Vst + (jt & 1) * KV_SZ;

        // ---- S = Q K^T : warp computes 32 x 64 (A-frags from registers) ----
        float sacc[2][8][4];
        #pragma unroll
        for (int mt = 0; mt < 2; mt++)
            #pragma unroll
            for (int nt = 0; nt < 8; nt++)
                #pragma unroll
                for (int j = 0; j < 4; j++) sacc[mt][nt][j] = 0.0f;

        #pragma unroll
        for (int kc = 0; kc < 8; kc++) {
            #pragma unroll
            for (int nt = 0; nt < 8; nt++) {
                uint32_t b0 = __float_as_uint(Ks[(nt * 8 + quad) * FSTR + kc * 8 + tq]);
                uint32_t b1 = __float_as_uint(Ks[(nt * 8 + quad) * FSTR + kc * 8 + tq + 4]);
                mma_tf32(sacc[0][nt], qf[kc][0], b0, b1);
                mma_tf32(sacc[1][nt], qf[kc][1], b0, b1);
            }
        }

        // ---- scale + causal mask ----
        const float scale = 0.125f;
        #pragma unroll
        for (int mt = 0; mt < 2; mt++) {
            #pragma unroll
            for (int nt = 0; nt < 8; nt++) {
                #pragma unroll
                for (int j = 0; j < 4; j++) {
                    float v = sacc[mt][nt][j] * scale;
                    if (diag) {
                        int c = k0 + nt * 8 + 2 * tq + (j & 1);
                        int r = q0 + w * 32 + mt * 16 + quad + (j >> 1) * 8;
                        if (c > r) v = -1e30f;
                    }
                    sacc[mt][nt][j] = v;
                }
            }
        }

        // ---- online softmax (per mt: rows quad, quad+8; reduce over tq) ----
        #pragma unroll
        for (int mt = 0; mt < 2; mt++) {
            float mx0 = -1e30f, mx1 = -1e30f;
            #pragma unroll
            for (int nt = 0; nt < 8; nt++) {
                mx0 = fmaxf(mx0, fmaxf(sacc[mt][nt][0], sacc[mt][nt][1]));
                mx1 = fmaxf(mx1, fmaxf(sacc[mt][nt][2], sacc[mt][nt][3]));
            }
            mx0 = fmaxf(mx0, __shfl_xor_sync(0xffffffffu, mx0, 1));
            mx0 = fmaxf(mx0, __shfl_xor_sync(0xffffffffu, mx0, 2));
            mx1 = fmaxf(mx1, __shfl_xor_sync(0xffffffffu, mx1, 1));
            mx1 = fmaxf(mx1, __shfl_xor_sync(0xffffffffu, mx1, 2));

            float mn0 = fmaxf(mi[mt][0], mx0), mn1 = fmaxf(mi[mt][1], mx1);
            float al0 = __expf(mi[mt][0] - mn0), al1 = __expf(mi[mt][1] - mn1);

            float sum0 = 0.0f, sum1 = 0.0f;
            #pragma unroll
            for (int nt = 0; nt < 8; nt++) {
                float p0 = __expf(sacc[mt][nt][0] - mn0);
                float p1 = __expf(sacc[mt][nt][1] - mn0);
                float p2 = __expf(sacc[mt][nt][2] - mn1);
                float p3 = __expf(sacc[mt][nt][3] - mn1);
                sum0 += p0 + p1;
                sum1 += p2 + p3;
                sacc[mt][nt][0] = p0; sacc[mt][nt][1] = p1;
                sacc[mt][nt][2] = p2; sacc[mt][nt][3] = p3;
            }
            sum0 += __shfl_xor_sync(0xffffffffu, sum0, 1);
            sum0 += __shfl_xor_sync(0xffffffffu, sum0, 2);
            sum1 += __shfl_xor_sync(0xffffffffu, sum1, 1);
            sum1 += __shfl_xor_sync(0xffffffffu, sum1, 2);

            li[mt][0] = li[mt][0] * al0 + sum0;  mi[mt][0] = mn0;
            li[mt][1] = li[mt][1] * al1 + sum1;  mi[mt][1] = mn1;
            #pragma unroll
            for (int nt = 0; nt < 8; nt++) {
                oacc[mt][nt][0] *= al0; oacc[mt][nt][1] *= al0;
                oacc[mt][nt][2] *= al1; oacc[mt][nt][3] *= al1;
            }
        }

        // ---- stage P (tf32 bits) into warp-private rows of Ps (=Qs) ----
        __syncwarp();
        #pragma unroll
        for (int mt = 0; mt < 2; mt++) {
            const int rowA = w * 32 + mt * 16 + quad;
            #pragma unroll
            for (int nt = 0; nt < 8; nt++) {
                float2 p01, p23;
                p01.x = f2tf32f(sacc[mt][nt][0]);
                p01.y = f2tf32f(sacc[mt][nt][1]);
                p23.x = f2tf32f(sacc[mt][nt][2]);
                p23.y = f2tf32f(sacc[mt][nt][3]);
                *(float2*)(Ps + rowA * FSTR + nt * 8 + 2 * tq) = p01;
                *(float2*)(Ps + (rowA + 8) * FSTR + nt * 8 + 2 * tq) = p23;
            }
        }
        __syncwarp();

        // ---- O += P V ----
        #pragma unroll
        for (int kc = 0; kc < 8; kc++) {
            uint32_t af[2][4];
            #pragma unroll
            for (int mt = 0; mt < 2; mt++) {
                const int rowA = w * 32 + mt * 16 + quad;
                af[mt][0] = __float_as_uint(Ps[rowA * FSTR + kc * 8 + tq]);
                af[mt][1] = __float_as_uint(Ps[(rowA + 8) * FSTR + kc * 8 + tq]);
                af[mt][2] = __float_as_uint(Ps[rowA * FSTR + kc * 8 + tq + 4]);
                af[mt][3] = __float_as_uint(Ps[(rowA + 8) * FSTR + kc * 8 + tq + 4]);
            }
            #pragma unroll
            for (int nt = 0; nt < 8; nt++) {
                uint32_t b0 = __float_as_uint(Vs[(kc * 8 + tq) * FSTR + nt * 8 + quad]);
                uint32_t b1 = __float_as_uint(Vs[(kc * 8 + tq + 4) * FSTR + nt * 8 + quad]);
                mma_tf32(oacc[0][nt], af[0], b0, b1);
                mma_tf32(oacc[1][nt], af[1], b0, b1);
            }
        }
    }

    // ---- epilogue: tf32-round (feeds proj gemm) ----
    #pragma unroll
    for (int mt = 0; mt < 2; mt++) {
        const float inv0 = 1.0f / li[mt][0];
        const float inv1 = 1.0f / li[mt][1];
        const size_t r0 = (size_t)b * TT + q0 + w * 32 + mt * 16 + quad;
        #pragma unroll
        for (int nt = 0; nt < 8; nt++) {
            const int col = h * HD + nt * 8 + 2 * tq;
            float2 v0, v1;
            v0.x = f2tf32f(oacc[mt][nt][0] * inv0);
            v0.y = f2tf32f(oacc[mt][nt][1] * inv0);
            v1.x = f2tf32f(oacc[mt][nt][2] * inv1);
            v1.y = f2tf32f(oacc[mt][nt][3] * inv1);
            *(float2*)(y + r0 * CC + col) = v0;
            *(float2*)(y + (r0 + 8) * CC + col) = v1;
        }
    }
}

// ---------------------------------------------------------------------------
// Launch
// ---------------------------------------------------------------------------
extern "C" void kernel_launch(void* const* d_in, const int* in_sizes, int n_in,
                              void* d_out, int out_size)
{
    const float* x     = (const float*)d_in[0];
    const float* Wqkv  = (const float*)d_in[1];
    const float* bqkv  = (const float*)d_in[2];
    const float* Wproj = (const float*)d_in[3];
    const float* bproj = (const float*)d_in[4];
    float* out = (float*)d_out;

    float *qkv, *ybuf, *xt, *wt;
    cudaGetSymbolAddress((void**)&qkv, g_qkv);
    cudaGetSymbolAddress((void**)&ybuf, g_y);
    cudaGetSymbolAddress((void**)&xt, g_xt);
    cudaGetSymbolAddress((void**)&wt, g_wt);
    float* wqkv32  = wt;
    float* wproj32 = wt + (size_t)CC * C3;

    const int smem_gemm = NSTAGE * (AS_SZ + BS_SZ) * sizeof(float);   // 107520
    cudaFuncSetAttribute(gemm_tf32mma<true>,
                         cudaFuncAttributeMaxDynamicSharedMemorySize, smem_gemm);
    cudaFuncSetAttribute(gemm_tf32mma<false>,
                         cudaFuncAttributeMaxDynamicSharedMemorySize, smem_gemm);

    const int smem_attn = (128 + 4 * 64) * FSTR * sizeof(float);      // 104448
    cudaFuncSetAttribute(flash_attn_mma,
                         cudaFuncAttributeMaxDynamicSharedMemorySize, smem_attn);

    // 0) tf32-round inputs/weights once.
    {
        int n4;
        n4 = (MM * CC) / 4;
        conv_tf32<<<(n4 + 255) / 256, 256>>>(x, xt, n4);
        n4 = (CC * C3) / 4;
        conv_tf32<<<(n4 + 255) / 256, 256>>>(Wqkv, wqkv32, n4);
        n4 = (CC * CC) / 4;
        conv_tf32<<<(n4 + 255) / 256, 256>>>(Wproj, wproj32, n4);
    }

    // 1) QKV projection (output tf32-rounded: feeds attention mma)
    gemm_tf32mma<true><<<dim3(C3 / BN, MM / BM), 256, smem_gemm>>>(
        xt, wqkv32, bqkv, qkv, MM, C3, CC);

    // 2) Causal flash attention -> ybuf (tf32-rounded: feeds proj mma)
    flash_attn_mma<<<dim3(TT / BQ, HH, BB), 128, smem_attn>>>(qkv, ybuf);

    // 3) Output projection (final output: exact fp32)
    gemm_tf32mma<false><<<dim3(CC / BN, MM / BM), 256, smem_gemm>>>(
        ybuf, wproj32, bproj, out, MM, CC, CC);
}

// round 12
// speedup vs baseline: 1.3184x; 1.2709x over previous
#include <cuda_runtime.h>
#include <cuda_fp16.h>
#include <math.h>
#include <stdint.h>

// Problem shape (fixed)
#define BB 4
#define TT 2048
#define CC 1024
#define HH 16
#define HD 64
#define MM (BB * TT)     // 8192 rows
#define C3 (3 * CC)      // 3072

// Scratch (device globals — allocation-free per harness rules)
__device__ float g_qkv[(size_t)MM * C3];   // 96 MB fp32 (tf32-rounded by QKV gemm)
__device__ float g_y[(size_t)MM * CC];     // reused as fp16 ybuf (16 MB used)
__device__ float g_xt[(size_t)MM * CC];    // reused as fp16 x (16 MB used)
__device__ float g_wt[(size_t)C3 * CC + (size_t)CC * CC];  // reused as fp16 W^T

// ---------------------------------------------------------------------------
// PTX helpers (baseline sm_80+ only: harness PTX target is compute_103,
// which rejects tcgen05/accelerated-arch instructions).
// ---------------------------------------------------------------------------
#define CP_ASYNC16(dst, src) \
    asm volatile("cp.async.cg.shared.global [%0], [%1], 16;\n" \
                 :: "r"(dst), "l"(src) : "memory")
#define CP_COMMIT()  asm volatile("cp.async.commit_group;\n" ::: "memory")
#define CP_WAIT1()   asm volatile("cp.async.wait_group 1;\n" ::: "memory")

__device__ __forceinline__ uint32_t smem_u32(const void* p) {
    uint32_t a;
    asm("{ .reg .u64 t; cvta.to.shared.u64 t, %1; cvt.u32.u64 %0, t; }"
        : "=r"(a) : "l"(p));
    return a;
}

__device__ __forceinline__ uint32_t f2tf32(float f) {
    uint32_t r;
    asm("cvt.rna.tf32.f32 %0, %1;" : "=r"(r) : "f"(f));
    return r;
}
__device__ __forceinline__ float f2tf32f(float f) {
    return __uint_as_float(f2tf32(f));
}

// tf32 mma (attention, unchanged)
__device__ __forceinline__ void mma_tf32(float c[4], const uint32_t a[4],
                                         uint32_t b0, uint32_t b1) {
    asm volatile(
        "mma.sync.aligned.m16n8k8.row.col.f32.tf32.tf32.f32 "
        "{%0,%1,%2,%3}, {%4,%5,%6,%7}, {%8,%9}, {%0,%1,%2,%3};"
        : "+f"(c[0]), "+f"(c[1]), "+f"(c[2]), "+f"(c[3])
        : "r"(a[0]), "r"(a[1]), "r"(a[2]), "r"(a[3]), "r"(b0), "r"(b1));
}

// f16 mma m16n8k16, fp32 accumulate (GEMMs)
__device__ __forceinline__ void mma_f16(float c[4], const uint32_t a[4],
                                        uint32_t b0, uint32_t b1) {
    asm volatile(
        "mma.sync.aligned.m16n8k16.row.col.f32.f16.f16.f32 "
        "{%0,%1,%2,%3}, {%4,%5,%6,%7}, {%8,%9}, {%0,%1,%2,%3};"
        : "+f"(c[0]), "+f"(c[1]), "+f"(c[2]), "+f"(c[3])
        : "r"(a[0]), "r"(a[1]), "r"(a[2]), "r"(a[3]), "r"(b0), "r"(b1));
}

// ---------------------------------------------------------------------------
// Conversion passes.
// ---------------------------------------------------------------------------
// fp32 -> fp16 elementwise (x). n8 = count/8.
__global__ __launch_bounds__(256)
void conv_f16(const float* __restrict__ in, __half* __restrict__ out, int n8)
{
    int i = blockIdx.x * 256 + threadIdx.x;
    if (i < n8) {
        float4 a = ((const float4*)in)[i * 2];
        float4 b = ((const float4*)in)[i * 2 + 1];
        __half2 h[4];
        h[0] = __floats2half2_rn(a.x, a.y);
        h[1] = __floats2half2_rn(a.z, a.w);
        h[2] = __floats2half2_rn(b.x, b.y);
        h[3] = __floats2half2_rn(b.z, b.w);
        ((float4*)out)[i] = *(float4*)h;
    }
}

// Transpose + fp16 convert: out[n][k] = (half)in[k][n]. in is [R=K][Cc=N].
__global__ __launch_bounds__(256)
void transpose_f16(const float* __restrict__ in, __half* __restrict__ out,
                   int R, int Cc)
{
    __shared__ float t[32][33];
    int c0 = blockIdx.x * 32, r0 = blockIdx.y * 32;
    int x = threadIdx.x, y = threadIdx.y;
    #pragma unroll
    for (int i = 0; i < 32; i += 8)
        t[y + i][x] = in[(size_t)(r0 + y + i) * Cc + c0 + x];
    __syncthreads();
    #pragma unroll
    for (int i = 0; i < 32; i += 8)
        out[(size_t)(c0 + y + i) * R + r0 + x] = __float2half(t[x][y + i]);
}

// ---------------------------------------------------------------------------
// FP16 mma.sync GEMM: C[M,N](fp32) = A[M,K](f16) @ BT[N,K](f16)^T + bias.
// CTA 128x128x32, 256 threads (8 warps: 2M x 4N), warp tile 64x32.
// 3-stage cp.async, one syncthreads per 32-k tile.
// Smem: A [m][k] 40-half stride; B [n][k] 40-half stride (both bank-bijective
// for fragment reads: (quad*20+tq) mod 32 is a lane bijection).
// OUT_TF32: round output to tf32 (feeds attention's tf32 mma).
// ---------------------------------------------------------------------------
#define BM 128
#define BN 128
#define BKH 32      // k per tile (halves)
#define HSTR 40     // halves per smem row (20 b32)
#define NSTAGE 3
#define TILE_H (128 * HSTR)          // halves per A or B stage (5120)
#define STAGE_B32 (TILE_H / 2)       // 2560 b32 per stage

template<bool OUT_TF32>
__global__ __launch_bounds__(256, 2)
void gemm_f16mma(const __half* __restrict__ A, const __half* __restrict__ BT,
                 const float* __restrict__ bias, float* __restrict__ C,
                 int M, int N, int K)
{
    extern __shared__ __align__(16) __half smh[];
    __half* Asm = smh;                       // [NSTAGE][128][HSTR]
    __half* Bsm = smh + NSTAGE * TILE_H;     // [NSTAGE][128][HSTR]

    const int tid  = threadIdx.x;
    const int wid  = tid >> 5;
    const int lane = tid & 31;
    const int quad = lane >> 2;
    const int tq   = lane & 3;
    const int warpM = wid & 1;     // 0..1 -> 64 rows
    const int warpN = wid >> 1;    // 0..3 -> 32 cols
    const int row0 = blockIdx.y * BM;
    const int col0 = blockIdx.x * BN;

    float acc[4][4][4];
    #pragma unroll
    for (int mt = 0; mt < 4; mt++)
        #pragma unroll
        for (int nt = 0; nt < 4; nt++)
            #pragma unroll
            for (int j = 0; j < 4; j++) acc[mt][nt][j] = 0.0f;

    const uint32_t sAu = smem_u32(Asm);
    const uint32_t sBu = smem_u32(Bsm);

    // Per k-tile: A tile 128x32 halves = 512 16B chunks; B same.
    // 256 threads -> 2 chunks each per tile per operand.
    auto load_tile = [&](int kt) {
        const int s = kt % NSTAGE;
        const int k0 = kt * BKH;
        #pragma unroll
        for (int i = 0; i < 2; i++) {
            const int id  = tid + i * 256;       // 0..511
            const int r   = id >> 2;             // 0..127
            const int kc  = (id & 3) << 3;       // 0,8,16,24 halves
            CP_ASYNC16(sAu + (uint32_t)(s * TILE_H + r * HSTR + kc) * 2,
                       A + (size_t)(row0 + r) * K + k0 + kc);
            CP_ASYNC16(sBu + (uint32_t)(s * TILE_H + r * HSTR + kc) * 2,
                       BT + (size_t)(col0 + r) * K + k0 + kc);
        }
        CP_COMMIT();
    };

    const int NKT = K / BKH;   // 32
    load_tile(0);
    load_tile(1);

    for (int kt = 0; kt < NKT; kt++) {
        CP_WAIT1();
        __syncthreads();
        if (kt + 2 < NKT) load_tile(kt + 2);

        const uint32_t* as = (const uint32_t*)(Asm + (kt % NSTAGE) * TILE_H);
        const uint32_t* bs = (const uint32_t*)(Bsm + (kt % NSTAGE) * TILE_H);

        #pragma unroll
        for (int ks = 0; ks < 2; ks++) {       // two k16 steps per 32-k tile
            uint32_t af[4][4];
            #pragma unroll
            for (int mt = 0; mt < 4; mt++) {
                const int mb = warpM * 64 + mt * 16 + quad;
                const int cb = ks * 8 + tq;    // b32 index within row (20 total)
                af[mt][0] = as[mb * 20 + cb];
                af[mt][1] = as[(mb + 8) * 20 + cb];
                af[mt][2] = as[mb * 20 + cb + 4];
                af[mt][3] = as[(mb + 8) * 20 + cb + 4];
            }
            #pragma unroll
            for (int nt = 0; nt < 4; nt++) {
                const int n0 = warpN * 32 + nt * 8 + quad;
                const int cb = ks * 8 + tq;
                uint32_t b0 = bs[n0 * 20 + cb];
                uint32_t b1 = bs[n0 * 20 + cb + 4];
                #pragma unroll
                for (int mt = 0; mt < 4; mt++)
                    mma_f16(acc[mt][nt], af[mt], b0, b1);
            }
        }
    }

    // Epilogue
    #pragma unroll
    for (int mt = 0; mt < 4; mt++) {
        #pragma unroll
        for (int half = 0; half < 2; half++) {
            const int row = row0 + warpM * 64 + mt * 16 + quad + half * 8;
            float* crow = C + (size_t)row * N;
            #pragma unroll
            for (int nt = 0; nt < 4; nt++) {
                const int col = col0 + warpN * 32 + nt * 8 + 2 * tq;
                float2 v;
                v.x = acc[mt][nt][half * 2 + 0] + __ldg(bias + col);
                v.y = acc[mt][nt][half * 2 + 1] + __ldg(bias + col + 1);
                if (OUT_TF32) { v.x = f2tf32f(v.x); v.y = f2tf32f(v.y); }
                *(float2*)(crow + col) = v;
            }
        }
    }
}

// ---------------------------------------------------------------------------
// Flash attention, tf32 mma.sync (R11 version — passing, ~332us).
// BQ=128, 128 threads (4 warps). Q frags hoisted; P aliases Qs; K/V cp.async
// double-buffered. NEW: epilogue writes fp16 ybuf (feeds fp16 proj GEMM).
// ---------------------------------------------------------------------------
#define FSTR 68
#define BQ 128
#define KV_SZ (64 * FSTR)

__global__ __launch_bounds__(128, 2)
void flash_attn_mma(const float* __restrict__ qkv, __half* __restrict__ y)
{
    extern __shared__ float sm[];
    float* Qs  = sm;                    // [128][68] prologue staging
    float* Ps  = sm;                    // alias — Qs dead after frag hoist
    float* Kst = sm + 128 * FSTR;       // [2][64][68]
    float* Vst = Kst + 2 * KV_SZ;       // [2][64][68]

    const int tid  = threadIdx.x;
    const int w    = tid >> 5;
    const int lane = tid & 31;
    const int quad = lane >> 2;
    const int tq   = lane & 3;

    const int b = blockIdx.z, h = blockIdx.y;
    const int q0 = (gridDim.x - 1 - blockIdx.x) * BQ;

    const float* base = qkv + (size_t)b * TT * C3 + h * HD;
    const float* Qg = base;
    const float* Kg = base + CC;
    const float* Vg = base + 2 * CC;

    const uint32_t sKu = smem_u32(Kst);
    const uint32_t sVu = smem_u32(Vst);

    #pragma unroll
    for (int it = 0; it < 16; it++) {
        int idx = tid + it * 128;
        int r  = idx >> 4;
        int dc = (idx & 15) << 2;
        *(float4*)(Qs + r * FSTR + dc) =
            *(const float4*)(Qg + (size_t)(q0 + r) * C3 + dc);
    }

    auto load_kv = [&](int jt) {
        const int s = jt & 1;
        const int k0 = jt << 6;
        #pragma unroll
        for (int it = 0; it < 8; it++) {
            int idx = tid + it * 128;
            int r  = idx >> 4;
            int dc = (idx & 15) << 2;
            const uint32_t off = (uint32_t)(s * KV_SZ + r * FSTR + dc) * 4;
            CP_ASYNC16(sKu + off, Kg + (size_t)(k0 + r) * C3 + dc);
            CP_ASYNC16(sVu + off, Vg + (size_t)(k0 + r) * C3 + dc);
        }
        CP_COMMIT();
    };

    __syncthreads();
    load_kv(0);

    uint32_t qf[8][2][4];
    #pragma unroll
    for (int kc = 0; kc < 8; kc++)
        #pragma unroll
        for (int mt = 0; mt < 2; mt++) {
            const int rowA = w * 32 + mt * 16 + quad;
            qf[kc][mt][0] = __float_as_uint(Qs[rowA * FSTR + kc * 8 + tq]);
            qf[kc][mt][1] = __float_as_uint(Qs[(rowA + 8) * FSTR + kc * 8 + tq]);
            qf[kc][mt][2] = __float_as_uint(Qs[rowA * FSTR + kc * 8 + tq + 4]);
            qf[kc][mt][3] = __float_as_uint(Qs[(rowA + 8) * FSTR + kc * 8 + tq + 4]);
        }

    float mi[2][2], li[2][2];
    #pragma unroll
    for (int mt = 0; mt < 2; mt++) {
        mi[mt][0] = -1e30f; mi[mt][1] = -1e30f;
        li[mt][0] = 0.0f;   li[mt][1] = 0.0f;
    }
    float oacc[2][8][4];
    #pragma unroll
    for (int mt = 0; mt < 2; mt++)
        #pragma unroll
        for (int nt = 0; nt < 8; nt++)
            #pragma unroll
            for (int j = 0; j < 4; j++) oacc[mt][nt][j] = 0.0f;

    const int ntile = (q0 >> 6) + 2;
    for (int jt = 0; jt < ntile; jt++) {
        const int k0 = jt << 6;
        __syncthreads();
        if (jt + 1 < ntile) load_kv(jt + 1);
        CP_WAIT1();
        __syncthreads();

        if (jt == ntile - 1 && w < 2) continue;

        const bool diag = (w < 2) ? (jt == ntile - 2) : (jt == ntile - 1);
        const float* Ks = Kst + (jt & 1) * KV_SZ;
        const float* Vs = Vst + (jt & 1) * KV_SZ;

        float sacc[2][8][4];
        #pragma unroll
        for (int mt = 0; mt < 2; mt++)
            #pragma unroll
            for (int nt = 0; nt < 8; nt++)
                #pragma unroll
                for (int j = 0; j < 4; j++) sacc[mt][nt][j] = 0.0f;

        #pragma unroll
        for (int kc = 0; kc < 8; kc++) {
            #pragma unroll
            for (int nt = 0; nt < 8; nt++) {
                uint32_t b0 = __float_as_uint(Ks[(nt * 8 + quad) * FSTR + kc * 8 + tq]);
                uint32_t b1 = __float_as_uint(Ks[(nt * 8 + quad) * FSTR + kc * 8 + tq + 4]);
                mma_tf32(sacc[0][nt], qf[kc][0], b0, b1);
                mma_tf32(sacc[1][nt], qf[kc][1], b0, b1);
            }
        }

        const float scale = 0.125f;
        #pragma unroll
        for (int mt = 0; mt < 2; mt++) {
            #pragma unroll
            for (int nt = 0; nt < 8; nt++) {
                #pragma unroll
                for (int j = 0; j < 4; j++) {
                    float v = sacc[mt][nt][j] * scale;
                    if (diag) {
                        int c = k0 + nt * 8 + 2 * tq + (j & 1);
                        int r = q0 + w * 32 + mt * 16 + quad + (j >> 1) * 8;
                        if (c > r) v = -1e30f;
                    }
                    sacc[mt][nt][j] = v;
                }
            }
        }

        #pragma unroll
        for (int mt = 0; mt < 2; mt++) {
            float mx0 = -1e30f, mx1 = -1e30f;
            #pragma unroll
            for (int nt = 0; nt < 8; nt++) {
                mx0 = fmaxf(mx0, fmaxf(sacc[mt][nt][0], sacc[mt][nt][1]));
                mx1 = fmaxf(mx1, fmaxf(sacc[mt][nt][2], sacc[mt][nt][3]));
            }
            mx0 = fmaxf(mx0, __shfl_xor_sync(0xffffffffu, mx0, 1));
            mx0 = fmaxf(mx0, __shfl_xor_sync(0xffffffffu, mx0, 2));
            mx1 = fmaxf(mx1, __shfl_xor_sync(0xffffffffu, mx1, 1));
            mx1 = fmaxf(mx1, __shfl_xor_sync(0xffffffffu, mx1, 2));

            float mn0 = fmaxf(mi[mt][0], mx0), mn1 = fmaxf(mi[mt][1], mx1);
            float al0 = __expf(mi[mt][0] - mn0), al1 = __expf(mi[mt][1] - mn1);

            float sum0 = 0.0f, sum1 = 0.0f;
            #pragma unroll
            for (int nt = 0; nt < 8; nt++) {
                float p0 = __expf(sacc[mt][nt][0] - mn0);
                float p1 = __expf(sacc[mt][nt][1] - mn0);
                float p2 = __expf(sacc[mt][nt][2] - mn1);
                float p3 = __expf(sacc[mt][nt][3] - mn1);
                sum0 += p0 + p1;
                sum1 += p2 + p3;
                sacc[mt][nt][0] = p0; sacc[mt][nt][1] = p1;
                sacc[mt][nt][2] = p2; sacc[mt][nt][3] = p3;
            }
            sum0 += __shfl_xor_sync(0xffffffffu, sum0, 1);
            sum0 += __shfl_xor_sync(0xffffffffu, sum0, 2);
            sum1 += __shfl_xor_sync(0xffffffffu, sum1, 1);
            sum1 += __shfl_xor_sync(0xffffffffu, sum1, 2);

            li[mt][0] = li[mt][0] * al0 + sum0;  mi[mt][0] = mn0;
            li[mt][1] = li[mt][1] * al1 + sum1;  mi[mt][1] = mn1;
            #pragma unroll
            for (int nt = 0; nt < 8; nt++) {
                oacc[mt][nt][0] *= al0; oacc[mt][nt][1] *= al0;
                oacc[mt][nt][2] *= al1; oacc[mt][nt][3] *= al1;
            }
        }

        __syncwarp();
        #pragma unroll
        for (int mt = 0; mt < 2; mt++) {
            const int rowA = w * 32 + mt * 16 + quad;
            #pragma unroll
            for (int nt = 0; nt < 8; nt++) {
                float2 p01, p23;
                p01.x = f2tf32f(sacc[mt][nt][0]);
                p01.y = f2tf32f(sacc[mt][nt][1]);
                p23.x = f2tf32f(sacc[mt][nt][2]);
                p23.y = f2tf32f(sacc[mt][nt][3]);
                *(float2*)(Ps + rowA * FSTR + nt * 8 + 2 * tq) = p01;
                *(float2*)(Ps + (rowA + 8) * FSTR + nt * 8 + 2 * tq) = p23;
            }
        }
        __syncwarp();

        #pragma unroll
        for (int kc = 0; kc < 8; kc++) {
            uint32_t af[2][4];
            #pragma unroll
            for (int mt = 0; mt < 2; mt++) {
                const int rowA = w * 32 + mt * 16 + quad;
                af[mt][0] = __float_as_uint(Ps[rowA * FSTR + kc * 8 + tq]);
                af[mt][1] = __float_as_uint(Ps[(rowA + 8) * FSTR + kc * 8 + tq]);
                af[mt][2] = __float_as_uint(Ps[rowA * FSTR + kc * 8 + tq + 4]);
                af[mt][3] = __float_as_uint(Ps[(rowA + 8) * FSTR + kc * 8 + tq + 4]);
            }
            #pragma unroll
            for (int nt = 0; nt < 8; nt++) {
                uint32_t b0 = __float_as_uint(Vs[(kc * 8 + tq) * FSTR + nt * 8 + quad]);
                uint32_t b1 = __float_as_uint(Vs[(kc * 8 + tq + 4) * FSTR + nt * 8 + quad]);
                mma_tf32(oacc[0][nt], af[0], b0, b1);
                mma_tf32(oacc[1][nt], af[1], b0, b1);
            }
        }
    }

    // ---- epilogue: write fp16 ybuf (feeds fp16 proj GEMM) ----
    #pragma unroll
    for (int mt = 0; mt < 2; mt++) {
        const float inv0 = 1.0f / li[mt][0];
        const float inv1 = 1.0f / li[mt][1];
        const size_t r0 = (size_t)b * TT + q0 + w * 32 + mt * 16 + quad;
        #pragma unroll
        for (int nt = 0; nt < 8; nt++) {
            const int col = h * HD + nt * 8 + 2 * tq;
            __half2 v0 = __floats2half2_rn(oacc[mt][nt][0] * inv0,
                                           oacc[mt][nt][1] * inv0);
            __half2 v1 = __floats2half2_rn(oacc[mt][nt][2] * inv1,
                                           oacc[mt][nt][3] * inv1);
            *(__half2*)(y + r0 * CC + col) = v0;
            *(__half2*)(y + (r0 + 8) * CC + col) = v1;
        }
    }
}

// ---------------------------------------------------------------------------
// Launch
// ---------------------------------------------------------------------------
extern "C" void kernel_launch(void* const* d_in, const int* in_sizes, int n_in,
                              void* d_out, int out_size)
{
    const float* x     = (const float*)d_in[0];
    const float* Wqkv  = (const float*)d_in[1];
    const float* bqkv  = (const float*)d_in[2];
    const float* Wproj = (const float*)d_in[3];
    const float* bproj = (const float*)d_in[4];
    float* out = (float*)d_out;

    float *qkv, *ybuf, *xt, *wt;
    cudaGetSymbolAddress((void**)&qkv, g_qkv);
    cudaGetSymbolAddress((void**)&ybuf, g_y);
    cudaGetSymbolAddress((void**)&xt, g_xt);
    cudaGetSymbolAddress((void**)&wt, g_wt);
    __half* xh      = (__half*)xt;                       // [8192][1024]
    __half* yh      = (__half*)ybuf;                     // [8192][1024]
    __half* wqkvTh  = (__half*)wt;                       // [3072][1024]
    __half* wprojTh = (__half*)wt + (size_t)C3 * CC;     // [1024][1024]

    const int smem_gemm = NSTAGE * 2 * TILE_H * sizeof(__half);   // 61440
    cudaFuncSetAttribute(gemm_f16mma<true>,
                         cudaFuncAttributeMaxDynamicSharedMemorySize, smem_gemm);
    cudaFuncSetAttribute(gemm_f16mma<false>,
                         cudaFuncAttributeMaxDynamicSharedMemorySize, smem_gemm);

    const int smem_attn = (128 + 4 * 64) * FSTR * sizeof(float);  // 104448
    cudaFuncSetAttribute(flash_attn_mma,
                         cudaFuncAttributeMaxDynamicSharedMemorySize, smem_attn);

    // 0) Convert x to fp16; transpose+convert weights to fp16 [N][K].
    {
        int n8 = (MM * CC) / 8;
        conv_f16<<<(n8 + 255) / 256, 256>>>(x, xh, n8);
        transpose_f16<<<dim3(C3 / 32, CC / 32), dim3(32, 8)>>>(Wqkv, wqkvTh, CC, C3);
        transpose_f16<<<dim3(CC / 32, CC / 32), dim3(32, 8)>>>(Wproj, wprojTh, CC, CC);
    }

    // 1) QKV projection (f16 mma; output tf32-rounded fp32 for attention)
    gemm_f16mma<true><<<dim3(C3 / BN, MM / BM), 256, smem_gemm>>>(
        xh, wqkvTh, bqkv, qkv, MM, C3, CC);

    // 2) Causal flash attention (tf32 mma) -> fp16 ybuf
    flash_attn_mma<<<dim3(TT / BQ, HH, BB), 128, smem_attn>>>(qkv, yh);

    // 3) Output projection (f16 mma; exact fp32 out)
    gemm_f16mma<false><<<dim3(CC / BN, MM / BM), 256, smem_gemm>>>(
        yh, wprojTh, bproj, out, MM, CC, CC);
}

// round 13
// speedup vs baseline: 1.7368x; 1.3173x over previous
#include <cuda_runtime.h>
#include <cuda_fp16.h>
#include <math.h>
#include <stdint.h>

// Problem shape (fixed)
#define BB 4
#define TT 2048
#define CC 1024
#define HH 16
#define HD 64
#define MM (BB * TT)     // 8192 rows
#define C3 (3 * CC)      // 3072

// Scratch (device globals — allocation-free per harness rules)
// g_qkv as halves: [0 .. MM*C3) = qkv fp16 (48MB); [MM*C3 .. MM*C3+MM*CC) = vT fp16.
__device__ float g_qkv[(size_t)MM * C3];   // 96 MB raw
__device__ float g_y[(size_t)MM * CC];     // reused as fp16 ybuf
__device__ float g_xt[(size_t)MM * CC];    // reused as fp16 x
__device__ float g_wt[(size_t)C3 * CC + (size_t)CC * CC];  // fp16 W^T

// ---------------------------------------------------------------------------
// PTX helpers (baseline sm_80+ only: harness PTX target is compute_103,
// which rejects tcgen05/accelerated-arch instructions).
// ---------------------------------------------------------------------------
#define CP_ASYNC16(dst, src) \
    asm volatile("cp.async.cg.shared.global [%0], [%1], 16;\n" \
                 :: "r"(dst), "l"(src) : "memory")
#define CP_COMMIT()  asm volatile("cp.async.commit_group;\n" ::: "memory")
#define CP_WAIT1()   asm volatile("cp.async.wait_group 1;\n" ::: "memory")

__device__ __forceinline__ uint32_t smem_u32(const void* p) {
    uint32_t a;
    asm("{ .reg .u64 t; cvta.to.shared.u64 t, %1; cvt.u32.u64 %0, t; }"
        : "=r"(a) : "l"(p));
    return a;
}

// f16 mma m16n8k16, fp32 accumulate
__device__ __forceinline__ void mma_f16(float c[4], const uint32_t a[4],
                                        uint32_t b0, uint32_t b1) {
    asm volatile(
        "mma.sync.aligned.m16n8k16.row.col.f32.f16.f16.f32 "
        "{%0,%1,%2,%3}, {%4,%5,%6,%7}, {%8,%9}, {%0,%1,%2,%3};"
        : "+f"(c[0]), "+f"(c[1]), "+f"(c[2]), "+f"(c[3])
        : "r"(a[0]), "r"(a[1]), "r"(a[2]), "r"(a[3]), "r"(b0), "r"(b1));
}

// ---------------------------------------------------------------------------
// Conversion passes.
// ---------------------------------------------------------------------------
__global__ __launch_bounds__(256)
void conv_f16(const float* __restrict__ in, __half* __restrict__ out, int n8)
{
    int i = blockIdx.x * 256 + threadIdx.x;
    if (i < n8) {
        float4 a = ((const float4*)in)[i * 2];
        float4 b = ((const float4*)in)[i * 2 + 1];
        __half2 h[4];
        h[0] = __floats2half2_rn(a.x, a.y);
        h[1] = __floats2half2_rn(a.z, a.w);
        h[2] = __floats2half2_rn(b.x, b.y);
        h[3] = __floats2half2_rn(b.z, b.w);
        ((float4*)out)[i] = *(float4*)h;
    }
}

// Transpose + fp16 convert weights: out[n][k] = (half)in[k][n]. in [R=K][Cc=N].
__global__ __launch_bounds__(256)
void transpose_f16(const float* __restrict__ in, __half* __restrict__ out,
                   int R, int Cc)
{
    __shared__ float t[32][33];
    int c0 = blockIdx.x * 32, r0 = blockIdx.y * 32;
    int x = threadIdx.x, y = threadIdx.y;
    #pragma unroll
    for (int i = 0; i < 32; i += 8)
        t[y + i][x] = in[(size_t)(r0 + y + i) * Cc + c0 + x];
    __syncthreads();
    #pragma unroll
    for (int i = 0; i < 32; i += 8)
        out[(size_t)(c0 + y + i) * R + r0 + x] = __float2half(t[x][y + i]);
}

// V transpose (fp16 -> fp16): vT[(b*H+h)*HD + d][t] = qkv_h[b*T+t][2C + h*HD + d]
__global__ __launch_bounds__(256)
void transpose_v(const __half* __restrict__ qkvh, __half* __restrict__ vT)
{
    __shared__ __half t[32][33];
    const int t0 = blockIdx.x * 32;
    const int d0 = blockIdx.y * 32;
    const int z  = blockIdx.z;            // b*HH + h
    const int b  = z >> 4, h = z & 15;
    const int x = threadIdx.x, y = threadIdx.y;
    const __half* src = qkvh + (size_t)(b * TT) * C3 + 2 * CC + h * HD;
    #pragma unroll
    for (int i = 0; i < 32; i += 8)
        t[y + i][x] = src[(size_t)(t0 + y + i) * C3 + d0 + x];
    __syncthreads();
    __half* dst = vT + ((size_t)z * HD) * TT;
    #pragma unroll
    for (int i = 0; i < 32; i += 8)
        dst[(size_t)(d0 + y + i) * TT + t0 + x] = t[x][y + i];
}

// ---------------------------------------------------------------------------
// FP16 mma.sync GEMM: C[M,N] = A[M,K](f16) @ BT[N,K](f16)^T + bias.
// CTA 128x128x32, 256 threads (8 warps: 2M x 4N), warp tile 64x32.
// OUT_F16: write fp16 (qkv buffer); else fp32.
// ---------------------------------------------------------------------------
#define BM 128
#define BN 128
#define BKH 32      // k per tile (halves)
#define HSTR 40     // halves per smem row (20 b32)
#define NSTAGE 3
#define TILE_H (128 * HSTR)

template<bool OUT_F16>
__global__ __launch_bounds__(256, 2)
void gemm_f16mma(const __half* __restrict__ A, const __half* __restrict__ BT,
                 const float* __restrict__ bias, void* __restrict__ Cout,
                 int M, int N, int K)
{
    extern __shared__ __align__(16) __half smh[];
    __half* Asm = smh;
    __half* Bsm = smh + NSTAGE * TILE_H;

    const int tid  = threadIdx.x;
    const int wid  = tid >> 5;
    const int lane = tid & 31;
    const int quad = lane >> 2;
    const int tq   = lane & 3;
    const int warpM = wid & 1;
    const int warpN = wid >> 1;
    const int row0 = blockIdx.y * BM;
    const int col0 = blockIdx.x * BN;

    float acc[4][4][4];
    #pragma unroll
    for (int mt = 0; mt < 4; mt++)
        #pragma unroll
        for (int nt = 0; nt < 4; nt++)
            #pragma unroll
            for (int j = 0; j < 4; j++) acc[mt][nt][j] = 0.0f;

    const uint32_t sAu = smem_u32(Asm);
    const uint32_t sBu = smem_u32(Bsm);

    auto load_tile = [&](int kt) {
        const int s = kt % NSTAGE;
        const int k0 = kt * BKH;
        #pragma unroll
        for (int i = 0; i < 2; i++) {
            const int id  = tid + i * 256;
            const int r   = id >> 2;
            const int kc  = (id & 3) << 3;
            CP_ASYNC16(sAu + (uint32_t)(s * TILE_H + r * HSTR + kc) * 2,
                       A + (size_t)(row0 + r) * K + k0 + kc);
            CP_ASYNC16(sBu + (uint32_t)(s * TILE_H + r * HSTR + kc) * 2,
                       BT + (size_t)(col0 + r) * K + k0 + kc);
        }
        CP_COMMIT();
    };

    const int NKT = K / BKH;
    load_tile(0);
    load_tile(1);

    for (int kt = 0; kt < NKT; kt++) {
        CP_WAIT1();
        __syncthreads();
        if (kt + 2 < NKT) load_tile(kt + 2);

        const uint32_t* as = (const uint32_t*)(Asm + (kt % NSTAGE) * TILE_H);
        const uint32_t* bs = (const uint32_t*)(Bsm + (kt % NSTAGE) * TILE_H);

        #pragma unroll
        for (int ks = 0; ks < 2; ks++) {
            uint32_t af[4][4];
            #pragma unroll
            for (int mt = 0; mt < 4; mt++) {
                const int mb = warpM * 64 + mt * 16 + quad;
                const int cb = ks * 8 + tq;
                af[mt][0] = as[mb * 20 + cb];
                af[mt][1] = as[(mb + 8) * 20 + cb];
                af[mt][2] = as[mb * 20 + cb + 4];
                af[mt][3] = as[(mb + 8) * 20 + cb + 4];
            }
            #pragma unroll
            for (int nt = 0; nt < 4; nt++) {
                const int n0 = warpN * 32 + nt * 8 + quad;
                const int cb = ks * 8 + tq;
                uint32_t b0 = bs[n0 * 20 + cb];
                uint32_t b1 = bs[n0 * 20 + cb + 4];
                #pragma unroll
                for (int mt = 0; mt < 4; mt++)
                    mma_f16(acc[mt][nt], af[mt], b0, b1);
            }
        }
    }

    #pragma unroll
    for (int mt = 0; mt < 4; mt++) {
        #pragma unroll
        for (int half = 0; half < 2; half++) {
            const int row = row0 + warpM * 64 + mt * 16 + quad + half * 8;
            #pragma unroll
            for (int nt = 0; nt < 4; nt++) {
                const int col = col0 + warpN * 32 + nt * 8 + 2 * tq;
                float vx = acc[mt][nt][half * 2 + 0] + __ldg(bias + col);
                float vy = acc[mt][nt][half * 2 + 1] + __ldg(bias + col + 1);
                if (OUT_F16) {
                    __half* crow = (__half*)Cout + (size_t)row * N;
                    *(__half2*)(crow + col) = __floats2half2_rn(vx, vy);
                } else {
                    float* crow = (float*)Cout + (size_t)row * N;
                    float2 v; v.x = vx; v.y = vy;
                    *(float2*)(crow + col) = v;
                }
            }
        }
    }
}

// ---------------------------------------------------------------------------
// Flash attention, FP16 mma.sync (m16n8k16). BQ=128, 128 threads (4 warps),
// warp owns 32 q rows. KV tiles of 64, cp.async double-buffered.
// Q/K from fp16 qkv; V from pre-transposed vT [d][t] fp16 (B operand needs
// kv contiguous). Q frags hoisted to regs; P (fp16) aliases Q staging.
// Strides 72 halves (36 b32): fragment patterns bank-bijective.
// Smem: Q/P 128x72h + 2x(K 64x72h) + 2x(V^T 64x72h) = 55296 B -> 2 CTAs/SM.
// ---------------------------------------------------------------------------
#define BQ 128
#define HS2 72                 // halves per smem row
#define B32S 36                // b32 per smem row
#define KV_H (64 * HS2)        // halves per K (or V) stage

__global__ __launch_bounds__(128, 2)
void flash_attn_f16(const __half* __restrict__ qkvh,
                    const __half* __restrict__ vT,
                    __half* __restrict__ y)
{
    extern __shared__ __align__(16) __half smh[];
    __half* Qs  = smh;                  // [128][72] staging; P aliases
    __half* Ps  = smh;
    __half* Kst = smh + 128 * HS2;      // [2][64][72]
    __half* Vst = Kst + 2 * KV_H;       // [2][64][72]

    const int tid  = threadIdx.x;
    const int w    = tid >> 5;
    const int lane = tid & 31;
    const int quad = lane >> 2;
    const int tq   = lane & 3;

    const int b = blockIdx.z, h = blockIdx.y;
    const int q0 = (gridDim.x - 1 - blockIdx.x) * BQ;   // heavy tiles first

    const __half* Qg = qkvh + (size_t)b * TT * C3 + h * HD;
    const __half* Kg = Qg + CC;
    const __half* Vg = vT + ((size_t)(b * HH + h) * HD) * TT;   // [d][t]

    const uint32_t sQu = smem_u32(Qs);
    const uint32_t sKu = smem_u32(Kst);
    const uint32_t sVu = smem_u32(Vst);

    // Prologue: stage Q tile (128 rows x 64 halves) via cp.async.
    #pragma unroll
    for (int it = 0; it < 8; it++) {
        int idx = tid + it * 128;        // 0..1023
        int r  = idx >> 3;               // 0..127
        int hc = (idx & 7) << 3;         // 0..56 halves
        CP_ASYNC16(sQu + (uint32_t)(r * HS2 + hc) * 2,
                   Qg + (size_t)(q0 + r) * C3 + hc);
    }
    CP_COMMIT();

    // Async K/V^T tile loader: stage jt&1. K rows = kv; V rows = d.
    auto load_kv = [&](int jt) {
        const int s = jt & 1;
        const int k0 = jt << 6;
        #pragma unroll
        for (int it = 0; it < 4; it++) {
            int idx = tid + it * 128;    // 0..511
            int r  = idx >> 3;           // 0..63
            int hc = (idx & 7) << 3;     // 0..56
            const uint32_t off = (uint32_t)(s * KV_H + r * HS2 + hc) * 2;
            CP_ASYNC16(sKu + off, Kg + (size_t)(k0 + r) * C3 + hc);
            CP_ASYNC16(sVu + off, Vg + (size_t)r * TT + k0 + hc);
        }
        CP_COMMIT();
    };

    load_kv(0);
    // Wait for Q (2 groups pending: Q, kv0 -> wait until <=1 left = Q done).
    CP_WAIT1();
    __syncthreads();

    // Hoist Q fragments (4 k16 steps x 2 mt x 4 b32 = 32 regs).
    uint32_t qf[4][2][4];
    {
        const uint32_t* qb = (const uint32_t*)Qs;
        #pragma unroll
        for (int kc = 0; kc < 4; kc++)
            #pragma unroll
            for (int mt = 0; mt < 2; mt++) {
                const int rowA = w * 32 + mt * 16 + quad;
                qf[kc][mt][0] = qb[rowA * B32S + kc * 8 + tq];
                qf[kc][mt][1] = qb[(rowA + 8) * B32S + kc * 8 + tq];
                qf[kc][mt][2] = qb[rowA * B32S + kc * 8 + tq + 4];
                qf[kc][mt][3] = qb[(rowA + 8) * B32S + kc * 8 + tq + 4];
            }
    }

    float mi[2][2], li[2][2];
    #pragma unroll
    for (int mt = 0; mt < 2; mt++) {
        mi[mt][0] = -1e30f; mi[mt][1] = -1e30f;
        li[mt][0] = 0.0f;   li[mt][1] = 0.0f;
    }
    float oacc[2][8][4];
    #pragma unroll
    for (int mt = 0; mt < 2; mt++)
        #pragma unroll
        for (int nt = 0; nt < 8; nt++)
            #pragma unroll
            for (int j = 0; j < 4; j++) oacc[mt][nt][j] = 0.0f;

    const int ntile = (q0 >> 6) + 2;
    for (int jt = 0; jt < ntile; jt++) {
        const int k0 = jt << 6;
        __syncthreads();                       // stage (jt+1)&1 + Ps free
        if (jt + 1 < ntile) load_kv(jt + 1);
        CP_WAIT1();                            // tile jt arrived
        __syncthreads();

        // Warps 0,1 fully masked on last tile (safe: last iteration only).
        if (jt == ntile - 1 && w < 2) continue;

        const bool diag = (w < 2) ? (jt == ntile - 2) : (jt == ntile - 1);
        const uint32_t* Kb = (const uint32_t*)(Kst + (jt & 1) * KV_H);
        const uint32_t* Vb = (const uint32_t*)(Vst + (jt & 1) * KV_H);

        // ---- S = Q K^T : warp computes 32 x 64 ----
        float sacc[2][8][4];
        #pragma unroll
        for (int mt = 0; mt < 2; mt++)
            #pragma unroll
            for (int nt = 0; nt < 8; nt++)
                #pragma unroll
                for (int j = 0; j < 4; j++) sacc[mt][nt][j] = 0.0f;

        #pragma unroll
        for (int kc = 0; kc < 4; kc++) {
            #pragma unroll
            for (int nt = 0; nt < 8; nt++) {
                uint32_t b0 = Kb[(nt * 8 + quad) * B32S + kc * 8 + tq];
                uint32_t b1 = Kb[(nt * 8 + quad) * B32S + kc * 8 + tq + 4];
                mma_f16(sacc[0][nt], qf[kc][0], b0, b1);
                mma_f16(sacc[1][nt], qf[kc][1], b0, b1);
            }
        }

        // ---- scale + causal mask ----
        const float scale = 0.125f;
        #pragma unroll
        for (int mt = 0; mt < 2; mt++) {
            #pragma unroll
            for (int nt = 0; nt < 8; nt++) {
                #pragma unroll
                for (int j = 0; j < 4; j++) {
                    float v = sacc[mt][nt][j] * scale;
                    if (diag) {
                        int c = k0 + nt * 8 + 2 * tq + (j & 1);
                        int r = q0 + w * 32 + mt * 16 + quad + (j >> 1) * 8;
                        if (c > r) v = -1e30f;
                    }
                    sacc[mt][nt][j] = v;
                }
            }
        }

        // ---- online softmax ----
        #pragma unroll
        for (int mt = 0; mt < 2; mt++) {
            float mx0 = -1e30f, mx1 = -1e30f;
            #pragma unroll
            for (int nt = 0; nt < 8; nt++) {
                mx0 = fmaxf(mx0, fmaxf(sacc[mt][nt][0], sacc[mt][nt][1]));
                mx1 = fmaxf(mx1, fmaxf(sacc[mt][nt][2], sacc[mt][nt][3]));
            }
            mx0 = fmaxf(mx0, __shfl_xor_sync(0xffffffffu, mx0, 1));
            mx0 = fmaxf(mx0, __shfl_xor_sync(0xffffffffu, mx0, 2));
            mx1 = fmaxf(mx1, __shfl_xor_sync(0xffffffffu, mx1, 1));
            mx1 = fmaxf(mx1, __shfl_xor_sync(0xffffffffu, mx1, 2));

            float mn0 = fmaxf(mi[mt][0], mx0), mn1 = fmaxf(mi[mt][1], mx1);
            float al0 = __expf(mi[mt][0] - mn0), al1 = __expf(mi[mt][1] - mn1);

            float sum0 = 0.0f, sum1 = 0.0f;
            #pragma unroll
            for (int nt = 0; nt < 8; nt++) {
                float p0 = __expf(sacc[mt][nt][0] - mn0);
                float p1 = __expf(sacc[mt][nt][1] - mn0);
                float p2 = __expf(sacc[mt][nt][2] - mn1);
                float p3 = __expf(sacc[mt][nt][3] - mn1);
                sum0 += p0 + p1;
                sum1 += p2 + p3;
                sacc[mt][nt][0] = p0; sacc[mt][nt][1] = p1;
                sacc[mt][nt][2] = p2; sacc[mt][nt][3] = p3;
            }
            sum0 += __shfl_xor_sync(0xffffffffu, sum0, 1);
            sum0 += __shfl_xor_sync(0xffffffffu, sum0, 2);
            sum1 += __shfl_xor_sync(0xffffffffu, sum1, 1);
            sum1 += __shfl_xor_sync(0xffffffffu, sum1, 2);

            li[mt][0] = li[mt][0] * al0 + sum0;  mi[mt][0] = mn0;
            li[mt][1] = li[mt][1] * al1 + sum1;  mi[mt][1] = mn1;
            #pragma unroll
            for (int nt = 0; nt < 8; nt++) {
                oacc[mt][nt][0] *= al0; oacc[mt][nt][1] *= al0;
                oacc[mt][nt][2] *= al1; oacc[mt][nt][3] *= al1;
            }
        }

        // ---- stage P (fp16) into warp-private rows of Ps (=Qs) ----
        __syncwarp();
        #pragma unroll
        for (int mt = 0; mt < 2; mt++) {
            const int rowA = w * 32 + mt * 16 + quad;
            #pragma unroll
            for (int nt = 0; nt < 8; nt++) {
                *(__half2*)(Ps + rowA * HS2 + nt * 8 + 2 * tq) =
                    __floats2half2_rn(sacc[mt][nt][0], sacc[mt][nt][1]);
                *(__half2*)(Ps + (rowA + 8) * HS2 + nt * 8 + 2 * tq) =
                    __floats2half2_rn(sacc[mt][nt][2], sacc[mt][nt][3]);
            }
        }
        __syncwarp();

        // ---- O += P V : A = P [q][kv] f16, B = V^T [d][kv] f16 ----
        const uint32_t* Pb = (const uint32_t*)Ps;
        #pragma unroll
        for (int kc = 0; kc < 4; kc++) {
            uint32_t af[2][4];
            #pragma unroll
            for (int mt = 0; mt < 2; mt++) {
                const int rowA = w * 32 + mt * 16 + quad;
                af[mt][0] = Pb[rowA * B32S + kc * 8 + tq];
                af[mt][1] = Pb[(rowA + 8) * B32S + kc * 8 + tq];
                af[mt][2] = Pb[rowA * B32S + kc * 8 + tq + 4];
                af[mt][3] = Pb[(rowA + 8) * B32S + kc * 8 + tq + 4];
            }
            #pragma unroll
            for (int nt = 0; nt < 8; nt++) {
                uint32_t b0 = Vb[(nt * 8 + quad) * B32S + kc * 8 + tq];
                uint32_t b1 = Vb[(nt * 8 + quad) * B32S + kc * 8 + tq + 4];
                mma_f16(oacc[0][nt], af[0], b0, b1);
                mma_f16(oacc[1][nt], af[1], b0, b1);
            }
        }
    }

    // ---- epilogue: write fp16 ybuf (feeds fp16 proj GEMM) ----
    #pragma unroll
    for (int mt = 0; mt < 2; mt++) {
        const float inv0 = 1.0f / li[mt][0];
        const float inv1 = 1.0f / li[mt][1];
        const size_t r0 = (size_t)b * TT + q0 + w * 32 + mt * 16 + quad;
        #pragma unroll
        for (int nt = 0; nt < 8; nt++) {
            const int col = h * HD + nt * 8 + 2 * tq;
            *(__half2*)(y + r0 * CC + col) =
                __floats2half2_rn(oacc[mt][nt][0] * inv0, oacc[mt][nt][1] * inv0);
            *(__half2*)(y + (r0 + 8) * CC + col) =
                __floats2half2_rn(oacc[mt][nt][2] * inv1, oacc[mt][nt][3] * inv1);
        }
    }
}

// ---------------------------------------------------------------------------
// Launch
// ---------------------------------------------------------------------------
extern "C" void kernel_launch(void* const* d_in, const int* in_sizes, int n_in,
                              void* d_out, int out_size)
{
    const float* x     = (const float*)d_in[0];
    const float* Wqkv  = (const float*)d_in[1];
    const float* bqkv  = (const float*)d_in[2];
    const float* Wproj = (const float*)d_in[3];
    const float* bproj = (const float*)d_in[4];
    float* out = (float*)d_out;

    float *qkv, *ybuf, *xt, *wt;
    cudaGetSymbolAddress((void**)&qkv, g_qkv);
    cudaGetSymbolAddress((void**)&ybuf, g_y);
    cudaGetSymbolAddress((void**)&xt, g_xt);
    cudaGetSymbolAddress((void**)&wt, g_wt);
    __half* qkvh    = (__half*)qkv;                      // [8192][3072] fp16
    __half* vTh     = (__half*)qkv + (size_t)MM * C3;    // [B*H*64][2048] fp16
    __half* xh      = (__half*)xt;
    __half* yh      = (__half*)ybuf;
    __half* wqkvTh  = (__half*)wt;
    __half* wprojTh = (__half*)wt + (size_t)C3 * CC;

    const int smem_gemm = NSTAGE * 2 * TILE_H * sizeof(__half);   // 61440
    cudaFuncSetAttribute(gemm_f16mma<true>,
                         cudaFuncAttributeMaxDynamicSharedMemorySize, smem_gemm);
    cudaFuncSetAttribute(gemm_f16mma<false>,
                         cudaFuncAttributeMaxDynamicSharedMemorySize, smem_gemm);

    const int smem_attn = (128 + 4 * 64) * HS2 * sizeof(__half);  // 55296
    cudaFuncSetAttribute(flash_attn_f16,
                         cudaFuncAttributeMaxDynamicSharedMemorySize, smem_attn);

    // 0) Convert x to fp16; transpose+convert weights to fp16 [N][K].
    {
        int n8 = (MM * CC) / 8;
        conv_f16<<<(n8 + 255) / 256, 256>>>(x, xh, n8);
        transpose_f16<<<dim3(C3 / 32, CC / 32), dim3(32, 8)>>>(Wqkv, wqkvTh, CC, C3);
        transpose_f16<<<dim3(CC / 32, CC / 32), dim3(32, 8)>>>(Wproj, wprojTh, CC, CC);
    }

    // 1) QKV projection (f16 mma; fp16 output)
    gemm_f16mma<true><<<dim3(C3 / BN, MM / BM), 256, smem_gemm>>>(
        xh, wqkvTh, bqkv, qkvh, MM, C3, CC);

    // 1b) Transpose V: vT[b,h,d,t] fp16
    transpose_v<<<dim3(TT / 32, HD / 32, BB * HH), dim3(32, 8)>>>(qkvh, vTh);

    // 2) Causal flash attention (f16 mma) -> fp16 ybuf
    flash_attn_f16<<<dim3(TT / BQ, HH, BB), 128, smem_attn>>>(qkvh, vTh, yh);

    // 3) Output projection (f16 mma; fp32 out)
    gemm_f16mma<false><<<dim3(CC / BN, MM / BM), 256, smem_gemm>>>(
        yh, wprojTh, bproj, out, MM, CC, CC);
}

// round 14
// speedup vs baseline: 1.8922x; 1.0895x over previous
#include <cuda_runtime.h>
#include <cuda_fp16.h>
#include <math.h>
#include <stdint.h>

// Problem shape (fixed)
#define BB 4
#define TT 2048
#define CC 1024
#define HH 16
#define HD 64
#define MM (BB * TT)     // 8192 rows
#define C3 (3 * CC)      // 3072

// Scratch (device globals — allocation-free per harness rules)
__device__ float g_qkv[(size_t)MM * C3];   // fp16 qkv (48MB) + fp16 vT (32MB)
__device__ float g_y[(size_t)MM * CC];     // fp16 ybuf
__device__ float g_xt[(size_t)MM * CC];    // fp16 x
__device__ float g_wt[(size_t)C3 * CC + (size_t)CC * CC];  // fp16 W^T

// ---------------------------------------------------------------------------
// PTX helpers (baseline features only: harness PTX target is compute_103,
// which rejects tcgen05/accelerated-arch instructions).
// ---------------------------------------------------------------------------
#define CP_ASYNC16(dst, src) \
    asm volatile("cp.async.cg.shared.global [%0], [%1], 16;\n" \
                 :: "r"(dst), "l"(src) : "memory")
#define CP_COMMIT()  asm volatile("cp.async.commit_group;\n" ::: "memory")
#define CP_WAIT1()   asm volatile("cp.async.wait_group 1;\n" ::: "memory")

__device__ __forceinline__ uint32_t smem_u32(const void* p) {
    uint32_t a;
    asm("{ .reg .u64 t; cvta.to.shared.u64 t, %1; cvt.u32.u64 %0, t; }"
        : "=r"(a) : "l"(p));
    return a;
}

// ldmatrix x4: four 8x8 b16 matrices; lane l supplies row address of matrix l/8.
__device__ __forceinline__ void ldsm4(uint32_t r[4], uint32_t addr) {
    asm volatile("ldmatrix.sync.aligned.m8n8.x4.shared.b16 {%0,%1,%2,%3}, [%4];"
                 : "=r"(r[0]), "=r"(r[1]), "=r"(r[2]), "=r"(r[3]) : "r"(addr));
}

// f16 mma m16n8k16, fp32 accumulate
__device__ __forceinline__ void mma_f16(float c[4], const uint32_t a[4],
                                        uint32_t b0, uint32_t b1) {
    asm volatile(
        "mma.sync.aligned.m16n8k16.row.col.f32.f16.f16.f32 "
        "{%0,%1,%2,%3}, {%4,%5,%6,%7}, {%8,%9}, {%0,%1,%2,%3};"
        : "+f"(c[0]), "+f"(c[1]), "+f"(c[2]), "+f"(c[3])
        : "r"(a[0]), "r"(a[1]), "r"(a[2]), "r"(a[3]), "r"(b0), "r"(b1));
}

// ---------------------------------------------------------------------------
// Conversion passes.
// ---------------------------------------------------------------------------
__global__ __launch_bounds__(256)
void conv_f16(const float* __restrict__ in, __half* __restrict__ out, int n8)
{
    int i = blockIdx.x * 256 + threadIdx.x;
    if (i < n8) {
        float4 a = ((const float4*)in)[i * 2];
        float4 b = ((const float4*)in)[i * 2 + 1];
        __half2 h[4];
        h[0] = __floats2half2_rn(a.x, a.y);
        h[1] = __floats2half2_rn(a.z, a.w);
        h[2] = __floats2half2_rn(b.x, b.y);
        h[3] = __floats2half2_rn(b.z, b.w);
        ((float4*)out)[i] = *(float4*)h;
    }
}

__global__ __launch_bounds__(256)
void transpose_f16(const float* __restrict__ in, __half* __restrict__ out,
                   int R, int Cc)
{
    __shared__ float t[32][33];
    int c0 = blockIdx.x * 32, r0 = blockIdx.y * 32;
    int x = threadIdx.x, y = threadIdx.y;
    #pragma unroll
    for (int i = 0; i < 32; i += 8)
        t[y + i][x] = in[(size_t)(r0 + y + i) * Cc + c0 + x];
    __syncthreads();
    #pragma unroll
    for (int i = 0; i < 32; i += 8)
        out[(size_t)(c0 + y + i) * R + r0 + x] = __float2half(t[x][y + i]);
}

// V transpose: vT[(b*H+h)*HD + d][t] = qkv_h[b*T+t][2C + h*HD + d]
__global__ __launch_bounds__(256)
void transpose_v(const __half* __restrict__ qkvh, __half* __restrict__ vT)
{
    __shared__ __half t[32][33];
    const int t0 = blockIdx.x * 32;
    const int d0 = blockIdx.y * 32;
    const int z  = blockIdx.z;
    const int b  = z >> 4, h = z & 15;
    const int x = threadIdx.x, y = threadIdx.y;
    const __half* src = qkvh + (size_t)(b * TT) * C3 + 2 * CC + h * HD;
    #pragma unroll
    for (int i = 0; i < 32; i += 8)
        t[y + i][x] = src[(size_t)(t0 + y + i) * C3 + d0 + x];
    __syncthreads();
    __half* dst = vT + ((size_t)z * HD) * TT;
    #pragma unroll
    for (int i = 0; i < 32; i += 8)
        dst[(size_t)(d0 + y + i) * TT + t0 + x] = t[x][y + i];
}

// ---------------------------------------------------------------------------
// FP16 mma.sync GEMM with ldmatrix fragment loads.
// CTA 128x128x32, 256 threads (8 warps: 2M x 4N), warp tile 64x32.
// ---------------------------------------------------------------------------
#define BM 128
#define BN 128
#define BKH 32      // k per tile (halves)
#define HSTR 40     // halves per smem row
#define NSTAGE 3
#define TILE_H (128 * HSTR)

template<bool OUT_F16>
__global__ __launch_bounds__(256, 2)
void gemm_f16mma(const __half* __restrict__ A, const __half* __restrict__ BT,
                 const float* __restrict__ bias, void* __restrict__ Cout,
                 int M, int N, int K)
{
    extern __shared__ __align__(16) __half smh[];
    __half* Asm = smh;
    __half* Bsm = smh + NSTAGE * TILE_H;

    const int tid  = threadIdx.x;
    const int wid  = tid >> 5;
    const int lane = tid & 31;
    const int quad = lane >> 2;
    const int tq   = lane & 3;
    const int warpM = wid & 1;
    const int warpN = wid >> 1;
    const int row0 = blockIdx.y * BM;
    const int col0 = blockIdx.x * BN;

    // ldmatrix lane-address components (constant per thread):
    const int aRowOff = (lane & 7) + ((lane >> 3) & 1) * 8;  // within m16
    const int aKOff   = (lane >> 4) * 8;                     // k-lo/k-hi
    const int bRowOff = ((lane >> 4) * 8) + (lane & 7);      // within n16 (2 tiles)
    const int bKOff   = ((lane >> 3) & 1) * 8;               // k-lo/k-hi

    float acc[4][4][4];
    #pragma unroll
    for (int mt = 0; mt < 4; mt++)
        #pragma unroll
        for (int nt = 0; nt < 4; nt++)
            #pragma unroll
            for (int j = 0; j < 4; j++) acc[mt][nt][j] = 0.0f;

    const uint32_t sAu = smem_u32(Asm);
    const uint32_t sBu = smem_u32(Bsm);

    auto load_tile = [&](int kt) {
        const int s = kt % NSTAGE;
        const int k0 = kt * BKH;
        #pragma unroll
        for (int i = 0; i < 2; i++) {
            const int id  = tid + i * 256;
            const int r   = id >> 2;
            const int kc  = (id & 3) << 3;
            CP_ASYNC16(sAu + (uint32_t)(s * TILE_H + r * HSTR + kc) * 2,
                       A + (size_t)(row0 + r) * K + k0 + kc);
            CP_ASYNC16(sBu + (uint32_t)(s * TILE_H + r * HSTR + kc) * 2,
                       BT + (size_t)(col0 + r) * K + k0 + kc);
        }
        CP_COMMIT();
    };

    const int NKT = K / BKH;
    load_tile(0);
    load_tile(1);

    for (int kt = 0; kt < NKT; kt++) {
        CP_WAIT1();
        __syncthreads();
        if (kt + 2 < NKT) load_tile(kt + 2);

        const uint32_t aBase = sAu + (uint32_t)((kt % NSTAGE) * TILE_H) * 2;
        const uint32_t bBase = sBu + (uint32_t)((kt % NSTAGE) * TILE_H) * 2;

        #pragma unroll
        for (int ks = 0; ks < 2; ks++) {
            uint32_t af[4][4];
            #pragma unroll
            for (int mt = 0; mt < 4; mt++) {
                const int row = warpM * 64 + mt * 16 + aRowOff;
                const int kh  = ks * 16 + aKOff;
                ldsm4(af[mt], aBase + (uint32_t)(row * HSTR + kh) * 2);
            }
            uint32_t bf[2][4];
            #pragma unroll
            for (int ntp = 0; ntp < 2; ntp++) {
                const int row = warpN * 32 + ntp * 16 + bRowOff;
                const int kh  = ks * 16 + bKOff;
                ldsm4(bf[ntp], bBase + (uint32_t)(row * HSTR + kh) * 2);
            }
            #pragma unroll
            for (int nt = 0; nt < 4; nt++) {
                uint32_t b0 = bf[nt >> 1][(nt & 1) * 2];
                uint32_t b1 = bf[nt >> 1][(nt & 1) * 2 + 1];
                #pragma unroll
                for (int mt = 0; mt < 4; mt++)
                    mma_f16(acc[mt][nt], af[mt], b0, b1);
            }
        }
    }

    #pragma unroll
    for (int mt = 0; mt < 4; mt++) {
        #pragma unroll
        for (int half = 0; half < 2; half++) {
            const int row = row0 + warpM * 64 + mt * 16 + quad + half * 8;
            #pragma unroll
            for (int nt = 0; nt < 4; nt++) {
                const int col = col0 + warpN * 32 + nt * 8 + 2 * tq;
                float vx = acc[mt][nt][half * 2 + 0] + __ldg(bias + col);
                float vy = acc[mt][nt][half * 2 + 1] + __ldg(bias + col + 1);
                if (OUT_F16) {
                    __half* crow = (__half*)Cout + (size_t)row * N;
                    *(__half2*)(crow + col) = __floats2half2_rn(vx, vy);
                } else {
                    float* crow = (float*)Cout + (size_t)row * N;
                    float2 v; v.x = vx; v.y = vy;
                    *(float2*)(crow + col) = v;
                }
            }
        }
    }
}

// ---------------------------------------------------------------------------
// Flash attention, FP16 mma + ldmatrix. BQ=128, 128 threads (4 warps).
// Q/K from fp16 qkv; V from pre-transposed vT [d][t]. Q frags hoisted;
// P (fp16) aliases Q staging. K/V cp.async double-buffered.
// Strides 72 halves: ldmatrix phases conflict-free (36 words; 4i mod 32).
// ---------------------------------------------------------------------------
#define BQ 128
#define HS2 72                 // halves per smem row
#define KV_H (64 * HS2)

__global__ __launch_bounds__(128, 2)
void flash_attn_f16(const __half* __restrict__ qkvh,
                    const __half* __restrict__ vT,
                    __half* __restrict__ y)
{
    extern __shared__ __align__(16) __half smh[];
    __half* Qs  = smh;                  // [128][72]; P aliases
    __half* Ps  = smh;
    __half* Kst = smh + 128 * HS2;      // [2][64][72]
    __half* Vst = Kst + 2 * KV_H;       // [2][64][72]

    const int tid  = threadIdx.x;
    const int w    = tid >> 5;
    const int lane = tid & 31;
    const int quad = lane >> 2;
    const int tq   = lane & 3;

    const int aRowOff = (lane & 7) + ((lane >> 3) & 1) * 8;
    const int aKOff   = (lane >> 4) * 8;
    const int bRowOff = ((lane >> 4) * 8) + (lane & 7);
    const int bKOff   = ((lane >> 3) & 1) * 8;

    const int b = blockIdx.z, h = blockIdx.y;
    const int q0 = (gridDim.x - 1 - blockIdx.x) * BQ;

    const __half* Qg = qkvh + (size_t)b * TT * C3 + h * HD;
    const __half* Kg = Qg + CC;
    const __half* Vg = vT + ((size_t)(b * HH + h) * HD) * TT;

    const uint32_t sQu = smem_u32(Qs);
    const uint32_t sKu = smem_u32(Kst);
    const uint32_t sVu = smem_u32(Vst);

    // Prologue: stage Q tile via cp.async.
    #pragma unroll
    for (int it = 0; it < 8; it++) {
        int idx = tid + it * 128;
        int r  = idx >> 3;
        int hc = (idx & 7) << 3;
        CP_ASYNC16(sQu + (uint32_t)(r * HS2 + hc) * 2,
                   Qg + (size_t)(q0 + r) * C3 + hc);
    }
    CP_COMMIT();

    auto load_kv = [&](int jt) {
        const int s = jt & 1;
        const int k0 = jt << 6;
        #pragma unroll
        for (int it = 0; it < 4; it++) {
            int idx = tid + it * 128;
            int r  = idx >> 3;
            int hc = (idx & 7) << 3;
            const uint32_t off = (uint32_t)(s * KV_H + r * HS2 + hc) * 2;
            CP_ASYNC16(sKu + off, Kg + (size_t)(k0 + r) * C3 + hc);
            CP_ASYNC16(sVu + off, Vg + (size_t)r * TT + k0 + hc);
        }
        CP_COMMIT();
    };

    load_kv(0);
    CP_WAIT1();          // Q staged (kv0 may be pending)
    __syncthreads();

    // Hoist Q fragments via ldmatrix (4 kc x 2 mt).
    uint32_t qf[4][2][4];
    #pragma unroll
    for (int kc = 0; kc < 4; kc++)
        #pragma unroll
        for (int mt = 0; mt < 2; mt++) {
            const int row = w * 32 + mt * 16 + aRowOff;
            const int kh  = kc * 16 + aKOff;
            ldsm4(qf[kc][mt], sQu + (uint32_t)(row * HS2 + kh) * 2);
        }

    float mi[2][2], li[2][2];
    #pragma unroll
    for (int mt = 0; mt < 2; mt++) {
        mi[mt][0] = -1e30f; mi[mt][1] = -1e30f;
        li[mt][0] = 0.0f;   li[mt][1] = 0.0f;
    }
    float oacc[2][8][4];
    #pragma unroll
    for (int mt = 0; mt < 2; mt++)
        #pragma unroll
        for (int nt = 0; nt < 8; nt++)
            #pragma unroll
            for (int j = 0; j < 4; j++) oacc[mt][nt][j] = 0.0f;

    const int ntile = (q0 >> 6) + 2;
    for (int jt = 0; jt < ntile; jt++) {
        const int k0 = jt << 6;
        __syncthreads();
        if (jt + 1 < ntile) load_kv(jt + 1);
        CP_WAIT1();
        __syncthreads();

        if (jt == ntile - 1 && w < 2) continue;

        const bool diag = (w < 2) ? (jt == ntile - 2) : (jt == ntile - 1);
        const uint32_t kBase = sKu + (uint32_t)((jt & 1) * KV_H) * 2;
        const uint32_t vBase = sVu + (uint32_t)((jt & 1) * KV_H) * 2;

        // ---- S = Q K^T ----
        float sacc[2][8][4];
        #pragma unroll
        for (int mt = 0; mt < 2; mt++)
            #pragma unroll
            for (int nt = 0; nt < 8; nt++)
                #pragma unroll
                for (int j = 0; j < 4; j++) sacc[mt][nt][j] = 0.0f;

        #pragma unroll
        for (int kc = 0; kc < 4; kc++) {
            #pragma unroll
            for (int ntp = 0; ntp < 4; ntp++) {
                uint32_t kf[4];
                const int row = ntp * 16 + bRowOff;
                const int kh  = kc * 16 + bKOff;
                ldsm4(kf, kBase + (uint32_t)(row * HS2 + kh) * 2);
                mma_f16(sacc[0][ntp * 2],     qf[kc][0], kf[0], kf[1]);
                mma_f16(sacc[1][ntp * 2],     qf[kc][1], kf[0], kf[1]);
                mma_f16(sacc[0][ntp * 2 + 1], qf[kc][0], kf[2], kf[3]);
                mma_f16(sacc[1][ntp * 2 + 1], qf[kc][1], kf[2], kf[3]);
            }
        }

        // ---- scale + causal mask ----
        const float scale = 0.125f;
        #pragma unroll
        for (int mt = 0; mt < 2; mt++) {
            #pragma unroll
            for (int nt = 0; nt < 8; nt++) {
                #pragma unroll
                for (int j = 0; j < 4; j++) {
                    float v = sacc[mt][nt][j] * scale;
                    if (diag) {
                        int c = k0 + nt * 8 + 2 * tq + (j & 1);
                        int r = q0 + w * 32 + mt * 16 + quad + (j >> 1) * 8;
                        if (c > r) v = -1e30f;
                    }
                    sacc[mt][nt][j] = v;
                }
            }
        }

        // ---- online softmax ----
        #pragma unroll
        for (int mt = 0; mt < 2; mt++) {
            float mx0 = -1e30f, mx1 = -1e30f;
            #pragma unroll
            for (int nt = 0; nt < 8; nt++) {
                mx0 = fmaxf(mx0, fmaxf(sacc[mt][nt][0], sacc[mt][nt][1]));
                mx1 = fmaxf(mx1, fmaxf(sacc[mt][nt][2], sacc[mt][nt][3]));
            }
            mx0 = fmaxf(mx0, __shfl_xor_sync(0xffffffffu, mx0, 1));
            mx0 = fmaxf(mx0, __shfl_xor_sync(0xffffffffu, mx0, 2));
            mx1 = fmaxf(mx1, __shfl_xor_sync(0xffffffffu, mx1, 1));
            mx1 = fmaxf(mx1, __shfl_xor_sync(0xffffffffu, mx1, 2));

            float mn0 = fmaxf(mi[mt][0], mx0), mn1 = fmaxf(mi[mt][1], mx1);
            float al0 = __expf(mi[mt][0] - mn0), al1 = __expf(mi[mt][1] - mn1);

            float sum0 = 0.0f, sum1 = 0.0f;
            #pragma unroll
            for (int nt = 0; nt < 8; nt++) {
                float p0 = __expf(sacc[mt][nt][0] - mn0);
                float p1 = __expf(sacc[mt][nt][1] - mn0);
                float p2 = __expf(sacc[mt][nt][2] - mn1);
                float p3 = __expf(sacc[mt][nt][3] - mn1);
                sum0 += p0 + p1;
                sum1 += p2 + p3;
                sacc[mt][nt][0] = p0; sacc[mt][nt][1] = p1;
                sacc[mt][nt][2] = p2; sacc[mt][nt][3] = p3;
            }
            sum0 += __shfl_xor_sync(0xffffffffu, sum0, 1);
            sum0 += __shfl_xor_sync(0xffffffffu, sum0, 2);
            sum1 += __shfl_xor_sync(0xffffffffu, sum1, 1);
            sum1 += __shfl_xor_sync(0xffffffffu, sum1, 2);

            li[mt][0] = li[mt][0] * al0 + sum0;  mi[mt][0] = mn0;
            li[mt][1] = li[mt][1] * al1 + sum1;  mi[mt][1] = mn1;
            #pragma unroll
            for (int nt = 0; nt < 8; nt++) {
                oacc[mt][nt][0] *= al0; oacc[mt][nt][1] *= al0;
                oacc[mt][nt][2] *= al1; oacc[mt][nt][3] *= al1;
            }
        }

        // ---- stage P (fp16) into warp-private rows of Ps (=Qs) ----
        __syncwarp();
        #pragma unroll
        for (int mt = 0; mt < 2; mt++) {
            const int rowA = w * 32 + mt * 16 + quad;
            #pragma unroll
            for (int nt = 0; nt < 8; nt++) {
                *(__half2*)(Ps + rowA * HS2 + nt * 8 + 2 * tq) =
                    __floats2half2_rn(sacc[mt][nt][0], sacc[mt][nt][1]);
                *(__half2*)(Ps + (rowA + 8) * HS2 + nt * 8 + 2 * tq) =
                    __floats2half2_rn(sacc[mt][nt][2], sacc[mt][nt][3]);
            }
        }
        __syncwarp();

        // ---- O += P V : A = P [q][kv], B = V^T [d][kv] ----
        #pragma unroll
        for (int kc = 0; kc < 4; kc++) {
            uint32_t af[2][4];
            #pragma unroll
            for (int mt = 0; mt < 2; mt++) {
                const int row = w * 32 + mt * 16 + aRowOff;
                const int kh  = kc * 16 + aKOff;
                ldsm4(af[mt], sQu + (uint32_t)(row * HS2 + kh) * 2);
            }
            #pragma unroll
            for (int ntp = 0; ntp < 4; ntp++) {
                uint32_t vf[4];
                const int row = ntp * 16 + bRowOff;
                const int kh  = kc * 16 + bKOff;
                ldsm4(vf, vBase + (uint32_t)(row * HS2 + kh) * 2);
                mma_f16(oacc[0][ntp * 2],     af[0], vf[0], vf[1]);
                mma_f16(oacc[1][ntp * 2],     af[1], vf[0], vf[1]);
                mma_f16(oacc[0][ntp * 2 + 1], af[0], vf[2], vf[3]);
                mma_f16(oacc[1][ntp * 2 + 1], af[1], vf[2], vf[3]);
            }
        }
    }

    // ---- epilogue: write fp16 ybuf ----
    #pragma unroll
    for (int mt = 0; mt < 2; mt++) {
        const float inv0 = 1.0f / li[mt][0];
        const float inv1 = 1.0f / li[mt][1];
        const size_t r0 = (size_t)b * TT + q0 + w * 32 + mt * 16 + quad;
        #pragma unroll
        for (int nt = 0; nt < 8; nt++) {
            const int col = h * HD + nt * 8 + 2 * tq;
            *(__half2*)(y + r0 * CC + col) =
                __floats2half2_rn(oacc[mt][nt][0] * inv0, oacc[mt][nt][1] * inv0);
            *(__half2*)(y + (r0 + 8) * CC + col) =
                __floats2half2_rn(oacc[mt][nt][2] * inv1, oacc[mt][nt][3] * inv1);
        }
    }
}

// ---------------------------------------------------------------------------
// Launch
// ---------------------------------------------------------------------------
extern "C" void kernel_launch(void* const* d_in, const int* in_sizes, int n_in,
                              void* d_out, int out_size)
{
    const float* x     = (const float*)d_in[0];
    const float* Wqkv  = (const float*)d_in[1];
    const float* bqkv  = (const float*)d_in[2];
    const float* Wproj = (const float*)d_in[3];
    const float* bproj = (const float*)d_in[4];
    float* out = (float*)d_out;

    float *qkv, *ybuf, *xt, *wt;
    cudaGetSymbolAddress((void**)&qkv, g_qkv);
    cudaGetSymbolAddress((void**)&ybuf, g_y);
    cudaGetSymbolAddress((void**)&xt, g_xt);
    cudaGetSymbolAddress((void**)&wt, g_wt);
    __half* qkvh    = (__half*)qkv;
    __half* vTh     = (__half*)qkv + (size_t)MM * C3;
    __half* xh      = (__half*)xt;
    __half* yh      = (__half*)ybuf;
    __half* wqkvTh  = (__half*)wt;
    __half* wprojTh = (__half*)wt + (size_t)C3 * CC;

    const int smem_gemm = NSTAGE * 2 * TILE_H * sizeof(__half);   // 61440
    cudaFuncSetAttribute(gemm_f16mma<true>,
                         cudaFuncAttributeMaxDynamicSharedMemorySize, smem_gemm);
    cudaFuncSetAttribute(gemm_f16mma<false>,
                         cudaFuncAttributeMaxDynamicSharedMemorySize, smem_gemm);

    const int smem_attn = (128 + 4 * 64) * HS2 * sizeof(__half);  // 55296
    cudaFuncSetAttribute(flash_attn_f16,
                         cudaFuncAttributeMaxDynamicSharedMemorySize, smem_attn);

    // 0) Convert x to fp16; transpose+convert weights to fp16 [N][K].
    {
        int n8 = (MM * CC) / 8;
        conv_f16<<<(n8 + 255) / 256, 256>>>(x, xh, n8);
        transpose_f16<<<dim3(C3 / 32, CC / 32), dim3(32, 8)>>>(Wqkv, wqkvTh, CC, C3);
        transpose_f16<<<dim3(CC / 32, CC / 32), dim3(32, 8)>>>(Wproj, wprojTh, CC, CC);
    }

    // 1) QKV projection (f16 mma; fp16 output)
    gemm_f16mma<true><<<dim3(C3 / BN, MM / BM), 256, smem_gemm>>>(
        xh, wqkvTh, bqkv, qkvh, MM, C3, CC);

    // 1b) Transpose V: vT[b,h,d,t] fp16
    transpose_v<<<dim3(TT / 32, HD / 32, BB * HH), dim3(32, 8)>>>(qkvh, vTh);

    // 2) Causal flash attention (f16 mma + ldmatrix) -> fp16 ybuf
    flash_attn_f16<<<dim3(TT / BQ, HH, BB), 128, smem_attn>>>(qkvh, vTh, yh);

    // 3) Output projection (f16 mma; fp32 out)
    gemm_f16mma<false><<<dim3(CC / BN, MM / BM), 256, smem_gemm>>>(
        yh, wprojTh, bproj, out, MM, CC, CC);
}

// round 15
// speedup vs baseline: 2.0481x; 1.0824x over previous
#include <cuda_runtime.h>
#include <cuda_fp16.h>
#include <math.h>
#include <stdint.h>

// Problem shape (fixed)
#define BB 4
#define TT 2048
#define CC 1024
#define HH 16
#define HD 64
#define MM (BB * TT)     // 8192 rows
#define C3 (3 * CC)      // 3072

// Scratch (device globals — allocation-free per harness rules)
__device__ float g_qkv[(size_t)MM * C3];   // fp16 qkv (48MB) + fp16 vT (32MB)
__device__ float g_y[(size_t)MM * CC];     // fp16 ybuf
__device__ float g_xt[(size_t)MM * CC];    // fp16 x
__device__ float g_wt[(size_t)C3 * CC + (size_t)CC * CC];  // fp16 W^T

// ---------------------------------------------------------------------------
// PTX helpers (baseline features only: harness PTX target is compute_103,
// which rejects tcgen05/accelerated-arch instructions).
// ---------------------------------------------------------------------------
#define CP_ASYNC16(dst, src) \
    asm volatile("cp.async.cg.shared.global [%0], [%1], 16;\n" \
                 :: "r"(dst), "l"(src) : "memory")
#define CP_COMMIT()  asm volatile("cp.async.commit_group;\n" ::: "memory")
#define CP_WAIT1()   asm volatile("cp.async.wait_group 1;\n" ::: "memory")

__device__ __forceinline__ uint32_t smem_u32(const void* p) {
    uint32_t a;
    asm("{ .reg .u64 t; cvta.to.shared.u64 t, %1; cvt.u32.u64 %0, t; }"
        : "=r"(a) : "l"(p));
    return a;
}

__device__ __forceinline__ void ldsm4(uint32_t r[4], uint32_t addr) {
    asm volatile("ldmatrix.sync.aligned.m8n8.x4.shared.b16 {%0,%1,%2,%3}, [%4];"
                 : "=r"(r[0]), "=r"(r[1]), "=r"(r[2]), "=r"(r[3]) : "r"(addr));
}

__device__ __forceinline__ void mma_f16(float c[4], const uint32_t a[4],
                                        uint32_t b0, uint32_t b1) {
    asm volatile(
        "mma.sync.aligned.m16n8k16.row.col.f32.f16.f16.f32 "
        "{%0,%1,%2,%3}, {%4,%5,%6,%7}, {%8,%9}, {%0,%1,%2,%3};"
        : "+f"(c[0]), "+f"(c[1]), "+f"(c[2]), "+f"(c[3])
        : "r"(a[0]), "r"(a[1]), "r"(a[2]), "r"(a[3]), "r"(b0), "r"(b1));
}

// ---------------------------------------------------------------------------
// Conversion passes.
// ---------------------------------------------------------------------------
__global__ __launch_bounds__(256)
void conv_f16(const float* __restrict__ in, __half* __restrict__ out, int n8)
{
    int i = blockIdx.x * 256 + threadIdx.x;
    if (i < n8) {
        float4 a = ((const float4*)in)[i * 2];
        float4 b = ((const float4*)in)[i * 2 + 1];
        __half2 h[4];
        h[0] = __floats2half2_rn(a.x, a.y);
        h[1] = __floats2half2_rn(a.z, a.w);
        h[2] = __floats2half2_rn(b.x, b.y);
        h[3] = __floats2half2_rn(b.z, b.w);
        ((float4*)out)[i] = *(float4*)h;
    }
}

__global__ __launch_bounds__(256)
void transpose_f16(const float* __restrict__ in, __half* __restrict__ out,
                   int R, int Cc)
{
    __shared__ float t[32][33];
    int c0 = blockIdx.x * 32, r0 = blockIdx.y * 32;
    int x = threadIdx.x, y = threadIdx.y;
    #pragma unroll
    for (int i = 0; i < 32; i += 8)
        t[y + i][x] = in[(size_t)(r0 + y + i) * Cc + c0 + x];
    __syncthreads();
    #pragma unroll
    for (int i = 0; i < 32; i += 8)
        out[(size_t)(c0 + y + i) * R + r0 + x] = __float2half(t[x][y + i]);
}

// ---------------------------------------------------------------------------
// FP16 mma.sync GEMM with ldmatrix fragment loads.
// CTA 128x128x64, 256 threads (8 warps: 2M x 4N), warp tile 64x32.
// 3-stage cp.async (64-wide k), ONE syncthreads per k-tile (16 total).
// V_FUSE: output columns >= 2C are the V part of qkv — scatter them directly
// into the transposed vT[b,h,d,t] layout (removes the transpose_v kernel).
// ---------------------------------------------------------------------------
#define BM 128
#define BN 128
#define BKH 64      // k per tile (halves)
#define HSTR 72     // halves per smem row (36 b32: ldsm rows 4i mod 32 distinct)
#define NSTAGE 3
#define TILE_H (128 * HSTR)   // 9216 halves per operand stage

template<bool OUT_F16, bool V_FUSE>
__global__ __launch_bounds__(256, 2)
void gemm_f16mma(const __half* __restrict__ A, const __half* __restrict__ BT,
                 const float* __restrict__ bias, void* __restrict__ Cout,
                 __half* __restrict__ vTout,
                 int M, int N, int K)
{
    extern __shared__ __align__(16) __half smh[];
    __half* Asm = smh;
    __half* Bsm = smh + NSTAGE * TILE_H;

    const int tid  = threadIdx.x;
    const int wid  = tid >> 5;
    const int lane = tid & 31;
    const int quad = lane >> 2;
    const int tq   = lane & 3;
    const int warpM = wid & 1;
    const int warpN = wid >> 1;
    const int row0 = blockIdx.y * BM;
    const int col0 = blockIdx.x * BN;

    const int aRowOff = (lane & 7) + ((lane >> 3) & 1) * 8;
    const int aKOff   = (lane >> 4) * 8;
    const int bRowOff = ((lane >> 4) * 8) + (lane & 7);
    const int bKOff   = ((lane >> 3) & 1) * 8;

    float acc[4][4][4];
    #pragma unroll
    for (int mt = 0; mt < 4; mt++)
        #pragma unroll
        for (int nt = 0; nt < 4; nt++)
            #pragma unroll
            for (int j = 0; j < 4; j++) acc[mt][nt][j] = 0.0f;

    const uint32_t sAu = smem_u32(Asm);
    const uint32_t sBu = smem_u32(Bsm);

    auto load_tile = [&](int kt) {
        const int s = kt % NSTAGE;
        const int k0 = kt * BKH;
        #pragma unroll
        for (int i = 0; i < 4; i++) {
            const int id  = tid + i * 256;       // 0..1023
            const int r   = id >> 3;             // 0..127
            const int kc  = (id & 7) << 3;       // 0..56
            CP_ASYNC16(sAu + (uint32_t)(s * TILE_H + r * HSTR + kc) * 2,
                       A + (size_t)(row0 + r) * K + k0 + kc);
            CP_ASYNC16(sBu + (uint32_t)(s * TILE_H + r * HSTR + kc) * 2,
                       BT + (size_t)(col0 + r) * K + k0 + kc);
        }
        CP_COMMIT();
    };

    const int NKT = K / BKH;   // 16
    load_tile(0);
    load_tile(1);

    for (int kt = 0; kt < NKT; kt++) {
        CP_WAIT1();
        __syncthreads();
        if (kt + 2 < NKT) load_tile(kt + 2);

        const uint32_t aBase = sAu + (uint32_t)((kt % NSTAGE) * TILE_H) * 2;
        const uint32_t bBase = sBu + (uint32_t)((kt % NSTAGE) * TILE_H) * 2;

        #pragma unroll
        for (int ks = 0; ks < 4; ks++) {
            uint32_t af[4][4];
            #pragma unroll
            for (int mt = 0; mt < 4; mt++) {
                const int row = warpM * 64 + mt * 16 + aRowOff;
                const int kh  = ks * 16 + aKOff;
                ldsm4(af[mt], aBase + (uint32_t)(row * HSTR + kh) * 2);
            }
            uint32_t bf[2][4];
            #pragma unroll
            for (int ntp = 0; ntp < 2; ntp++) {
                const int row = warpN * 32 + ntp * 16 + bRowOff;
                const int kh  = ks * 16 + bKOff;
                ldsm4(bf[ntp], bBase + (uint32_t)(row * HSTR + kh) * 2);
            }
            #pragma unroll
            for (int nt = 0; nt < 4; nt++) {
                uint32_t b0 = bf[nt >> 1][(nt & 1) * 2];
                uint32_t b1 = bf[nt >> 1][(nt & 1) * 2 + 1];
                #pragma unroll
                for (int mt = 0; mt < 4; mt++)
                    mma_f16(acc[mt][nt], af[mt], b0, b1);
            }
        }
    }

    // Epilogue. For V_FUSE, a block is entirely Q/K (col0 < 2C) or V (col0 >= 2C).
    const bool vblock = V_FUSE && (col0 >= 2 * CC);
    #pragma unroll
    for (int mt = 0; mt < 4; mt++) {
        #pragma unroll
        for (int half = 0; half < 2; half++) {
            const int row = row0 + warpM * 64 + mt * 16 + quad + half * 8;
            #pragma unroll
            for (int nt = 0; nt < 4; nt++) {
                const int col = col0 + warpN * 32 + nt * 8 + 2 * tq;
                float vx = acc[mt][nt][half * 2 + 0] + __ldg(bias + col);
                float vy = acc[mt][nt][half * 2 + 1] + __ldg(bias + col + 1);
                if (OUT_F16) {
                    if (vblock) {
                        // scatter into vT[(b*H+h)*HD + d][t]
                        const int cc = col - 2 * CC;
                        const int hh = cc >> 6, dd = cc & 63;
                        const int bb = row >> 11, tt = row & 2047;
                        __half* dst = vTout + ((size_t)(bb * HH + hh) * HD) * TT;
                        dst[(size_t)dd * TT + tt]       = __float2half(vx);
                        dst[(size_t)(dd + 1) * TT + tt] = __float2half(vy);
                    } else {
                        __half* crow = (__half*)Cout + (size_t)row * N;
                        *(__half2*)(crow + col) = __floats2half2_rn(vx, vy);
                    }
                } else {
                    float* crow = (float*)Cout + (size_t)row * N;
                    float2 v; v.x = vx; v.y = vy;
                    *(float2*)(crow + col) = v;
                }
            }
        }
    }
}

// ---------------------------------------------------------------------------
// Flash attention, FP16 mma + ldmatrix. BQ=128, 128 threads (4 warps).
// Softmax in log2 domain (scale*log2e folded into one multiply; exp2f).
// Q/K from fp16 qkv; V from vT [d][t] (written by the QKV GEMM epilogue).
// Q frags hoisted; P (fp16) aliases Q staging; K/V cp.async double-buffered.
// ---------------------------------------------------------------------------
#define BQ 128
#define HS2 72
#define KV_H (64 * HS2)

__global__ __launch_bounds__(128, 2)
void flash_attn_f16(const __half* __restrict__ qkvh,
                    const __half* __restrict__ vT,
                    __half* __restrict__ y)
{
    extern __shared__ __align__(16) __half smh[];
    __half* Qs  = smh;
    __half* Ps  = smh;
    __half* Kst = smh + 128 * HS2;
    __half* Vst = Kst + 2 * KV_H;

    const int tid  = threadIdx.x;
    const int w    = tid >> 5;
    const int lane = tid & 31;
    const int quad = lane >> 2;
    const int tq   = lane & 3;

    const int aRowOff = (lane & 7) + ((lane >> 3) & 1) * 8;
    const int aKOff   = (lane >> 4) * 8;
    const int bRowOff = ((lane >> 4) * 8) + (lane & 7);
    const int bKOff   = ((lane >> 3) & 1) * 8;

    const int b = blockIdx.z, h = blockIdx.y;
    const int q0 = (gridDim.x - 1 - blockIdx.x) * BQ;

    const __half* Qg = qkvh + (size_t)b * TT * C3 + h * HD;
    const __half* Kg = Qg + CC;
    const __half* Vg = vT + ((size_t)(b * HH + h) * HD) * TT;

    const uint32_t sQu = smem_u32(Qs);
    const uint32_t sKu = smem_u32(Kst);
    const uint32_t sVu = smem_u32(Vst);

    #pragma unroll
    for (int it = 0; it < 8; it++) {
        int idx = tid + it * 128;
        int r  = idx >> 3;
        int hc = (idx & 7) << 3;
        CP_ASYNC16(sQu + (uint32_t)(r * HS2 + hc) * 2,
                   Qg + (size_t)(q0 + r) * C3 + hc);
    }
    CP_COMMIT();

    auto load_kv = [&](int jt) {
        const int s = jt & 1;
        const int k0 = jt << 6;
        #pragma unroll
        for (int it = 0; it < 4; it++) {
            int idx = tid + it * 128;
            int r  = idx >> 3;
            int hc = (idx & 7) << 3;
            const uint32_t off = (uint32_t)(s * KV_H + r * HS2 + hc) * 2;
            CP_ASYNC16(sKu + off, Kg + (size_t)(k0 + r) * C3 + hc);
            CP_ASYNC16(sVu + off, Vg + (size_t)r * TT + k0 + hc);
        }
        CP_COMMIT();
    };

    load_kv(0);
    CP_WAIT1();
    __syncthreads();

    uint32_t qf[4][2][4];
    #pragma unroll
    for (int kc = 0; kc < 4; kc++)
        #pragma unroll
        for (int mt = 0; mt < 2; mt++) {
            const int row = w * 32 + mt * 16 + aRowOff;
            const int kh  = kc * 16 + aKOff;
            ldsm4(qf[kc][mt], sQu + (uint32_t)(row * HS2 + kh) * 2);
        }

    float mi[2][2], li[2][2];
    #pragma unroll
    for (int mt = 0; mt < 2; mt++) {
        mi[mt][0] = -1e30f; mi[mt][1] = -1e30f;
        li[mt][0] = 0.0f;   li[mt][1] = 0.0f;
    }
    float oacc[2][8][4];
    #pragma unroll
    for (int mt = 0; mt < 2; mt++)
        #pragma unroll
        for (int nt = 0; nt < 8; nt++)
            #pragma unroll
            for (int j = 0; j < 4; j++) oacc[mt][nt][j] = 0.0f;

    const int ntile = (q0 >> 6) + 2;
    for (int jt = 0; jt < ntile; jt++) {
        const int k0 = jt << 6;
        __syncthreads();
        if (jt + 1 < ntile) load_kv(jt + 1);
        CP_WAIT1();
        __syncthreads();

        if (jt == ntile - 1 && w < 2) continue;

        const bool diag = (w < 2) ? (jt == ntile - 2) : (jt == ntile - 1);
        const uint32_t kBase = sKu + (uint32_t)((jt & 1) * KV_H) * 2;
        const uint32_t vBase = sVu + (uint32_t)((jt & 1) * KV_H) * 2;

        // ---- S = Q K^T ----
        float sacc[2][8][4];
        #pragma unroll
        for (int mt = 0; mt < 2; mt++)
            #pragma unroll
            for (int nt = 0; nt < 8; nt++)
                #pragma unroll
                for (int j = 0; j < 4; j++) sacc[mt][nt][j] = 0.0f;

        #pragma unroll
        for (int kc = 0; kc < 4; kc++) {
            #pragma unroll
            for (int ntp = 0; ntp < 4; ntp++) {
                uint32_t kf[4];
                const int row = ntp * 16 + bRowOff;
                const int kh  = kc * 16 + bKOff;
                ldsm4(kf, kBase + (uint32_t)(row * HS2 + kh) * 2);
                mma_f16(sacc[0][ntp * 2],     qf[kc][0], kf[0], kf[1]);
                mma_f16(sacc[1][ntp * 2],     qf[kc][1], kf[0], kf[1]);
                mma_f16(sacc[0][ntp * 2 + 1], qf[kc][0], kf[2], kf[3]);
                mma_f16(sacc[1][ntp * 2 + 1], qf[kc][1], kf[2], kf[3]);
            }
        }

        // ---- scale (log2 domain) + causal mask ----
        const float scl2 = 0.18033688011f;   // (1/8) * log2(e)
        #pragma unroll
        for (int mt = 0; mt < 2; mt++) {
            #pragma unroll
            for (int nt = 0; nt < 8; nt++) {
                #pragma unroll
                for (int j = 0; j < 4; j++) {
                    float v = sacc[mt][nt][j] * scl2;
                    if (diag) {
                        int c = k0 + nt * 8 + 2 * tq + (j & 1);
                        int r = q0 + w * 32 + mt * 16 + quad + (j >> 1) * 8;
                        if (c > r) v = -1e30f;
                    }
                    sacc[mt][nt][j] = v;
                }
            }
        }

        // ---- online softmax (base-2) ----
        #pragma unroll
        for (int mt = 0; mt < 2; mt++) {
            float mx0 = -1e30f, mx1 = -1e30f;
            #pragma unroll
            for (int nt = 0; nt < 8; nt++) {
                mx0 = fmaxf(mx0, fmaxf(sacc[mt][nt][0], sacc[mt][nt][1]));
                mx1 = fmaxf(mx1, fmaxf(sacc[mt][nt][2], sacc[mt][nt][3]));
            }
            mx0 = fmaxf(mx0, __shfl_xor_sync(0xffffffffu, mx0, 1));
            mx0 = fmaxf(mx0, __shfl_xor_sync(0xffffffffu, mx0, 2));
            mx1 = fmaxf(mx1, __shfl_xor_sync(0xffffffffu, mx1, 1));
            mx1 = fmaxf(mx1, __shfl_xor_sync(0xffffffffu, mx1, 2));

            float mn0 = fmaxf(mi[mt][0], mx0), mn1 = fmaxf(mi[mt][1], mx1);
            float al0 = exp2f(mi[mt][0] - mn0), al1 = exp2f(mi[mt][1] - mn1);

            float sum0 = 0.0f, sum1 = 0.0f;
            #pragma unroll
            for (int nt = 0; nt < 8; nt++) {
                float p0 = exp2f(sacc[mt][nt][0] - mn0);
                float p1 = exp2f(sacc[mt][nt][1] - mn0);
                float p2 = exp2f(sacc[mt][nt][2] - mn1);
                float p3 = exp2f(sacc[mt][nt][3] - mn1);
                sum0 += p0 + p1;
                sum1 += p2 + p3;
                sacc[mt][nt][0] = p0; sacc[mt][nt][1] = p1;
                sacc[mt][nt][2] = p2; sacc[mt][nt][3] = p3;
            }
            sum0 += __shfl_xor_sync(0xffffffffu, sum0, 1);
            sum0 += __shfl_xor_sync(0xffffffffu, sum0, 2);
            sum1 += __shfl_xor_sync(0xffffffffu, sum1, 1);
            sum1 += __shfl_xor_sync(0xffffffffu, sum1, 2);

            li[mt][0] = li[mt][0] * al0 + sum0;  mi[mt][0] = mn0;
            li[mt][1] = li[mt][1] * al1 + sum1;  mi[mt][1] = mn1;
            #pragma unroll
            for (int nt = 0; nt < 8; nt++) {
                oacc[mt][nt][0] *= al0; oacc[mt][nt][1] *= al0;
                oacc[mt][nt][2] *= al1; oacc[mt][nt][3] *= al1;
            }
        }

        // ---- stage P (fp16) into warp-private rows of Ps (=Qs) ----
        __syncwarp();
        #pragma unroll
        for (int mt = 0; mt < 2; mt++) {
            const int rowA = w * 32 + mt * 16 + quad;
            #pragma unroll
            for (int nt = 0; nt < 8; nt++) {
                *(__half2*)(Ps + rowA * HS2 + nt * 8 + 2 * tq) =
                    __floats2half2_rn(sacc[mt][nt][0], sacc[mt][nt][1]);
                *(__half2*)(Ps + (rowA + 8) * HS2 + nt * 8 + 2 * tq) =
                    __floats2half2_rn(sacc[mt][nt][2], sacc[mt][nt][3]);
            }
        }
        __syncwarp();

        // ---- O += P V ----
        #pragma unroll
        for (int kc = 0; kc < 4; kc++) {
            uint32_t af[2][4];
            #pragma unroll
            for (int mt = 0; mt < 2; mt++) {
                const int row = w * 32 + mt * 16 + aRowOff;
                const int kh  = kc * 16 + aKOff;
                ldsm4(af[mt], sQu + (uint32_t)(row * HS2 + kh) * 2);
            }
            #pragma unroll
            for (int ntp = 0; ntp < 4; ntp++) {
                uint32_t vf[4];
                const int row = ntp * 16 + bRowOff;
                const int kh  = kc * 16 + bKOff;
                ldsm4(vf, vBase + (uint32_t)(row * HS2 + kh) * 2);
                mma_f16(oacc[0][ntp * 2],     af[0], vf[0], vf[1]);
                mma_f16(oacc[1][ntp * 2],     af[1], vf[0], vf[1]);
                mma_f16(oacc[0][ntp * 2 + 1], af[0], vf[2], vf[3]);
                mma_f16(oacc[1][ntp * 2 + 1], af[1], vf[2], vf[3]);
            }
        }
    }

    // ---- epilogue: fp16 ybuf ----
    #pragma unroll
    for (int mt = 0; mt < 2; mt++) {
        const float inv0 = 1.0f / li[mt][0];
        const float inv1 = 1.0f / li[mt][1];
        const size_t r0 = (size_t)b * TT + q0 + w * 32 + mt * 16 + quad;
        #pragma unroll
        for (int nt = 0; nt < 8; nt++) {
            const int col = h * HD + nt * 8 + 2 * tq;
            *(__half2*)(y + r0 * CC + col) =
                __floats2half2_rn(oacc[mt][nt][0] * inv0, oacc[mt][nt][1] * inv0);
            *(__half2*)(y + (r0 + 8) * CC + col) =
                __floats2half2_rn(oacc[mt][nt][2] * inv1, oacc[mt][nt][3] * inv1);
        }
    }
}

// ---------------------------------------------------------------------------
// Launch
// ---------------------------------------------------------------------------
extern "C" void kernel_launch(void* const* d_in, const int* in_sizes, int n_in,
                              void* d_out, int out_size)
{
    const float* x     = (const float*)d_in[0];
    const float* Wqkv  = (const float*)d_in[1];
    const float* bqkv  = (const float*)d_in[2];
    const float* Wproj = (const float*)d_in[3];
    const float* bproj = (const float*)d_in[4];
    float* out = (float*)d_out;

    float *qkv, *ybuf, *xt, *wt;
    cudaGetSymbolAddress((void**)&qkv, g_qkv);
    cudaGetSymbolAddress((void**)&ybuf, g_y);
    cudaGetSymbolAddress((void**)&xt, g_xt);
    cudaGetSymbolAddress((void**)&wt, g_wt);
    __half* qkvh    = (__half*)qkv;
    __half* vTh     = (__half*)qkv + (size_t)MM * C3;
    __half* xh      = (__half*)xt;
    __half* yh      = (__half*)ybuf;
    __half* wqkvTh  = (__half*)wt;
    __half* wprojTh = (__half*)wt + (size_t)C3 * CC;

    const int smem_gemm = NSTAGE * 2 * TILE_H * sizeof(__half);   // 110592
    cudaFuncSetAttribute((const void*)gemm_f16mma<true, true>,
                         cudaFuncAttributeMaxDynamicSharedMemorySize, smem_gemm);
    cudaFuncSetAttribute((const void*)gemm_f16mma<false, false>,
                         cudaFuncAttributeMaxDynamicSharedMemorySize, smem_gemm);

    const int smem_attn = (128 + 4 * 64) * HS2 * sizeof(__half);  // 55296
    cudaFuncSetAttribute(flash_attn_f16,
                         cudaFuncAttributeMaxDynamicSharedMemorySize, smem_attn);

    // 0) Convert x to fp16; transpose+convert weights to fp16 [N][K].
    {
        int n8 = (MM * CC) / 8;
        conv_f16<<<(n8 + 255) / 256, 256>>>(x, xh, n8);
        transpose_f16<<<dim3(C3 / 32, CC / 32), dim3(32, 8)>>>(Wqkv, wqkvTh, CC, C3);
        transpose_f16<<<dim3(CC / 32, CC / 32), dim3(32, 8)>>>(Wproj, wprojTh, CC, CC);
    }

    // 1) QKV projection (f16 mma; Q/K -> qkvh, V scattered into vTh)
    gemm_f16mma<true, true><<<dim3(C3 / BN, MM / BM), 256, smem_gemm>>>(
        xh, wqkvTh, bqkv, qkvh, vTh, MM, C3, CC);

    // 2) Causal flash attention (f16 mma + ldmatrix, base-2 softmax) -> fp16 ybuf
    flash_attn_f16<<<dim3(TT / BQ, HH, BB), 128, smem_attn>>>(qkvh, vTh, yh);

    // 3) Output projection (f16 mma; fp32 out)
    gemm_f16mma<false, false><<<dim3(CC / BN, MM / BM), 256, smem_gemm>>>(
        yh, wprojTh, bproj, out, nullptr, MM, CC, CC);
}